// round 3
// baseline (speedup 1.0000x reference)
#include <cuda_runtime.h>
#include <math.h>
#include <stdint.h>

#define BB   8
#define NPT  1024
#define KNN  20
#define NROW (BB*NPT)

// ------------------------------------------------------------------ scratch
__device__ float g_neg[NROW*NPT];      // 32 MB distance matrix (per edge block, reused)
__device__ int   g_idx[NROW*KNN];
__device__ float g_xx [NROW];
__device__ float g_x0 [NROW*4];        // xyz, padded to 4 (4th = 0)
__device__ float g_s0 [NROW*128];      // sem
__device__ float g_h1 [NROW*64];
__device__ float g_h2 [NROW*64];
__device__ float g_h3 [NROW*128];
__device__ float g_t1 [NROW*64];
__device__ float g_t2 [NROW*64];
__device__ float g_t3 [NROW*128];
__device__ float g_emb[NROW*128];      // reused per set
__device__ float g_esum[BB*128];
__device__ float g_gc  [BB*128];
__device__ float g_e1  [BB*128];
__device__ float g_e2  [BB*128];

// ------------------------------------------------------------------ transpose input (B,C,N) -> point-major
__global__ void transpose_kernel(const float* __restrict__ in, float* __restrict__ x0, float* __restrict__ s0) {
    int j = blockIdx.x * blockDim.x + threadIdx.x;
    int total = BB * NPT * 132;
    if (j >= total) return;
    int c = j % 132;
    int n = (j / 132) % NPT;
    int b = j / (132 * NPT);
    if (c < 4) {
        x0[(b*NPT + n)*4 + c] = (c < 3) ? in[(b*131 + c)*NPT + n] : 0.0f;
    } else {
        int cc = c - 4;
        s0[(b*NPT + n)*128 + cc] = in[(b*131 + 3 + cc)*NPT + n];
    }
}

// ------------------------------------------------------------------ per-point squared norm
template <int CROW>
__global__ void xx_kernel(const float* __restrict__ X, float* __restrict__ xx) {
    int j = blockIdx.x * 256 + threadIdx.x;
    if (j >= NROW) return;
    const float* r = X + (long)j * CROW;
    float a = 0.f;
    #pragma unroll
    for (int c = 0; c < CROW; c++) a += r[c] * r[c];
    xx[j] = a;
}

// ------------------------------------------------------------------ neg distance matrix: 2*X.X^T - xx_n - xx_m
template <int CROW>
__global__ void dist_kernel(const float* __restrict__ X, const float* __restrict__ xx,
                            float* __restrict__ neg) {
    __shared__ float As[32][33];
    __shared__ float Bs[32][33];
    int b = blockIdx.z;
    int row0 = blockIdx.y * 32;
    int col0 = blockIdx.x * 32;
    int t = threadIdx.x;
    int tx = t & 31, ty = t >> 5;   // ty 0..7
    float acc[4] = {0.f, 0.f, 0.f, 0.f};
    for (int c0 = 0; c0 < CROW; c0 += 32) {
        int tc = (CROW - c0 < 32) ? (CROW - c0) : 32;
        for (int i = t; i < 32 * tc; i += 256) {
            int r = i / tc, c = i % tc;
            As[r][c] = X[((long)(b*NPT) + row0 + r) * CROW + c0 + c];
            Bs[r][c] = X[((long)(b*NPT) + col0 + r) * CROW + c0 + c];
        }
        __syncthreads();
        for (int c = 0; c < tc; c++) {
            float bv = Bs[tx][c];
            #pragma unroll
            for (int j = 0; j < 4; j++) acc[j] += As[ty + 8*j][c] * bv;
        }
        __syncthreads();
    }
    float xm = xx[b*NPT + col0 + tx];
    #pragma unroll
    for (int j = 0; j < 4; j++) {
        int n = row0 + ty + 8*j;
        neg[((long)(b*NPT) + n) * NPT + col0 + tx] = 2.f * acc[j] - xx[b*NPT + n] - xm;
    }
}

// ------------------------------------------------------------------ top-20 (largest neg_d, ties -> lowest index)
__global__ void topk_kernel(const float* __restrict__ neg, int* __restrict__ idxout) {
    __shared__ float srow[NPT];
    __shared__ unsigned long long wbest[8];
    int row = blockIdx.x;                 // b*NPT + n
    int t = threadIdx.x;
    for (int i = t; i < NPT; i += 256) srow[i] = neg[(long)row * NPT + i];
    __syncthreads();
    for (int sel = 0; sel < KNN; sel++) {
        unsigned long long best = 0ull;
        for (int i = t; i < NPT; i += 256) {
            float v = srow[i];
            unsigned u = __float_as_uint(v);
            u = (u & 0x80000000u) ? ~u : (u | 0x80000000u);   // order-preserving map
            unsigned long long key = ((unsigned long long)u << 32) | (unsigned)(NPT - 1 - i);
            if (key > best) best = key;
        }
        #pragma unroll
        for (int off = 16; off; off >>= 1) {
            unsigned long long o = __shfl_down_sync(0xffffffffu, best, off);
            if (o > best) best = o;
        }
        if ((t & 31) == 0) wbest[t >> 5] = best;
        __syncthreads();
        if (t == 0) {
            unsigned long long bb = wbest[0];
            #pragma unroll
            for (int j = 1; j < 8; j++) if (wbest[j] > bb) bb = wbest[j];
            int wi = NPT - 1 - (int)(bb & 0xffffffffull);
            idxout[row * KNN + sel] = wi;
            srow[wi] = -__int_as_float(0x7f800000);   // -inf
        }
        __syncthreads();
    }
}

// ------------------------------------------------------------------ fused gather + edge conv + BN + leaky + max_k
// out[b,n,o] = max_k leaky( a_o * (w1.nb_k + (w2-w1).ctr) + bias_o ),  a_o = g_o/sqrt(1+eps)
template <int CIN, int CROW, int COUT, int P>
__global__ __launch_bounds__(128)
void conv_kernel(const float* __restrict__ X, const int* __restrict__ idx,
                 const float* __restrict__ w, const float* __restrict__ gam,
                 const float* __restrict__ bet, float* __restrict__ out) {
    constexpr int TPP = COUT / 4;
    constexpr int CP  = CROW + 4;
    extern __shared__ float sm[];
    float* wt = sm;                          // [CIN][COUT]  (w1 transposed)
    float* wd = wt + CIN * COUT;             // [CIN][COUT]  (w2-w1 transposed)
    float* nb = wd + CIN * COUT;             // [P][21][CP]  (20 neighbors + ctr)
    int* sidx = (int*)(nb + P * 21 * CP);    // [P][KNN]

    int t = threadIdx.x;
    int b  = blockIdx.x / (NPT / P);
    int n0 = (blockIdx.x % (NPT / P)) * P;

    for (int i = t; i < CIN * COUT; i += 128) {
        int c = i / COUT, o = i % COUT;
        float w1 = w[o * (2*CIN) + c];
        wt[c * COUT + o] = w1;
        wd[c * COUT + o] = w[o * (2*CIN) + CIN + c] - w1;
    }
    for (int i = t; i < P * KNN; i += 128)
        sidx[i] = idx[((long)(b*NPT) + n0) * KNN + i];
    __syncthreads();

    constexpr int V4 = CROW / 4;
    for (int i = t; i < P * 21 * V4; i += 128) {
        int c4 = i % V4;
        int vec = i / V4;
        int p = vec / 21, k = vec % 21;
        int m = (k < KNN) ? sidx[p*KNN + k] : (n0 + p);
        float4 v = *(const float4*)&X[((long)(b*NPT) + m) * CROW + 4*c4];
        *(float4*)&nb[(p*21 + k) * CP + 4*c4] = v;
    }
    __syncthreads();

    int p  = t / TPP;
    int o4 = (t % TPP) * 4;
    float4 s[KNN];
    float4 u = make_float4(0.f, 0.f, 0.f, 0.f);
    #pragma unroll
    for (int k = 0; k < KNN; k++) s[k] = make_float4(0.f, 0.f, 0.f, 0.f);

    const float* nbp = nb + p * 21 * CP;
    for (int c = 0; c < CIN; c++) {
        float4 w4  = *(const float4*)&wt[c * COUT + o4];
        float4 wd4 = *(const float4*)&wd[c * COUT + o4];
        float ct = nbp[20 * CP + c];
        u.x += wd4.x * ct; u.y += wd4.y * ct; u.z += wd4.z * ct; u.w += wd4.w * ct;
        #pragma unroll
        for (int k = 0; k < KNN; k++) {
            float nv = nbp[k * CP + c];
            s[k].x += w4.x * nv; s[k].y += w4.y * nv;
            s[k].z += w4.z * nv; s[k].w += w4.w * nv;
        }
    }
    float4 mx = s[0], mn = s[0];
    #pragma unroll
    for (int k = 1; k < KNN; k++) {
        mx.x = fmaxf(mx.x, s[k].x); mx.y = fmaxf(mx.y, s[k].y);
        mx.z = fmaxf(mx.z, s[k].z); mx.w = fmaxf(mx.w, s[k].w);
        mn.x = fminf(mn.x, s[k].x); mn.y = fminf(mn.y, s[k].y);
        mn.z = fminf(mn.z, s[k].z); mn.w = fminf(mn.w, s[k].w);
    }
    float inv = rsqrtf(1.0f + 1e-5f);
    float4 gmv = *(const float4*)&gam[o4];
    float4 btv = *(const float4*)&bet[o4];
    float4 res;
    { float a = gmv.x*inv; float base = ((a>=0.f)?mx.x:mn.x) + u.x; float v = a*base + btv.x; res.x = v>=0.f?v:0.2f*v; }
    { float a = gmv.y*inv; float base = ((a>=0.f)?mx.y:mn.y) + u.y; float v = a*base + btv.y; res.y = v>=0.f?v:0.2f*v; }
    { float a = gmv.z*inv; float base = ((a>=0.f)?mx.z:mn.z) + u.z; float v = a*base + btv.z; res.z = v>=0.f?v:0.2f*v; }
    { float a = gmv.w*inv; float base = ((a>=0.f)?mx.w:mn.w) + u.w; float v = a*base + btv.w; res.w = v>=0.f?v:0.2f*v; }
    int n = n0 + p;
    *(float4*)&out[((long)(b*NPT) + n) * COUT + o4] = res;
}

// ------------------------------------------------------------------ ew conv on concat(H3,S3) -> emb (B*N,128)
__global__ __launch_bounds__(128)
void emb_kernel(const float* __restrict__ H3, const float* __restrict__ S3,
                const float* __restrict__ ew, const float* __restrict__ eg,
                const float* __restrict__ eb, float* __restrict__ emb) {
    extern __shared__ float sm[];
    float* wts  = sm;                 // [256][128]
    float* rows = wts + 256 * 128;    // [4][256]
    int t = threadIdx.x;
    for (int i = t; i < 256 * 128; i += 128) {
        int c = i / 128, o = i % 128;
        wts[c * 128 + o] = ew[o * 256 + c];
    }
    const int NITER = 8;
    int base = blockIdx.x * (4 * NITER);
    int pl = t / 32;
    int o4 = (t % 32) * 4;
    float inv = rsqrtf(1.0f + 1e-5f);
    for (int it = 0; it < NITER; it++) {
        __syncthreads();
        int p0 = base + it * 4;
        for (int i = t; i < 4 * 256; i += 128) {
            int pp = i / 256, c = i % 256;
            long pt = p0 + pp;
            rows[pp * 256 + c] = (c < 128) ? H3[pt * 128 + c] : S3[pt * 128 + c - 128];
        }
        __syncthreads();
        float4 acc = make_float4(0.f, 0.f, 0.f, 0.f);
        for (int c = 0; c < 256; c++) {
            float4 w4 = *(const float4*)&wts[c * 128 + o4];
            float xv = rows[pl * 256 + c];
            acc.x += w4.x * xv; acc.y += w4.y * xv;
            acc.z += w4.z * xv; acc.w += w4.w * xv;
        }
        float4 gmv = *(const float4*)&eg[o4];
        float4 btv = *(const float4*)&eb[o4];
        float4 r;
        { float v = gmv.x*inv*acc.x + btv.x; r.x = v>=0.f?v:0.2f*v; }
        { float v = gmv.y*inv*acc.y + btv.y; r.y = v>=0.f?v:0.2f*v; }
        { float v = gmv.z*inv*acc.z + btv.z; r.z = v>=0.f?v:0.2f*v; }
        { float v = gmv.w*inv*acc.w + btv.w; r.w = v>=0.f?v:0.2f*v; }
        long pt = p0 + pl;
        *(float4*)&emb[pt * 128 + o4] = r;
    }
}

// ------------------------------------------------------------------ attention pieces
__global__ void colsum_kernel(const float* __restrict__ emb, float* __restrict__ esum) {
    int b = blockIdx.x, f = threadIdx.x;
    float a = 0.f;
    for (int n = 0; n < NPT; n++) a += emb[((long)(b*NPT) + n) * 128 + f];
    esum[b * 128 + f] = a;
}

__global__ void gc_kernel(const float* __restrict__ esum, const float* __restrict__ att_w,
                          float* __restrict__ gc) {
    int b = blockIdx.x, gI = threadIdx.x;
    float a = 0.f;
    for (int f = 0; f < 128; f++) a += esum[b * 128 + f] * att_w[f * 128 + gI];
    gc[b * 128 + gI] = tanhf(a * (1.0f / NPT));
}

__global__ void sc_kernel(const float* __restrict__ emb, const float* __restrict__ gc,
                          float* __restrict__ att) {
    int warp = threadIdx.x >> 5, lane = threadIdx.x & 31;
    int pid = blockIdx.x * 4 + warp;          // 0..8191
    int b = pid >> 10;
    float a = 0.f;
    #pragma unroll
    for (int j = 0; j < 4; j++) {
        int f = lane + 32 * j;
        a += emb[(long)pid * 128 + f] * gc[b * 128 + f];
    }
    #pragma unroll
    for (int off = 16; off; off >>= 1) a += __shfl_down_sync(0xffffffffu, a, off);
    if (lane == 0) att[pid] = 1.0f / (1.0f + expf(-a));
}

__global__ void pool_kernel(const float* __restrict__ emb, const float* __restrict__ att,
                            float* __restrict__ e) {
    int b = blockIdx.x, f = threadIdx.x;
    float a = 0.f;
    for (int n = 0; n < NPT; n++)
        a += emb[((long)(b*NPT) + n) * 128 + f] * att[b * NPT + n];
    e[b * 128 + f] = a;
}

// ------------------------------------------------------------------ final scoring
__global__ void final_kernel(const float* __restrict__ e1, const float* __restrict__ e2,
                             const float* __restrict__ tn_w, const float* __restrict__ tn_wb,
                             const float* __restrict__ tn_bias, const float* __restrict__ fc1_w,
                             const float* __restrict__ fc1_b, const float* __restrict__ sc_w,
                             const float* __restrict__ sc_b, float* __restrict__ out) {
    __shared__ float e1s[128], e2s[128], red[128], ts[16], hs[16];
    int b = blockIdx.x, tid = threadIdx.x;
    e1s[tid] = e1[b * 128 + tid];
    e2s[tid] = e2[b * 128 + tid];
    __syncthreads();
    for (int tt = 0; tt < 16; tt++) {
        float inner = 0.f;
        const float* wrow = tn_w + (long)tid * 128 * 16 + tt;   // tn_w[f][g][tt], f=tid
        for (int gI = 0; gI < 128; gI++) inner += wrow[gI * 16] * e2s[gI];
        red[tid] = e1s[tid] * inner;
        __syncthreads();
        for (int s2 = 64; s2; s2 >>= 1) {
            if (tid < s2) red[tid] += red[tid + s2];
            __syncthreads();
        }
        if (tid == 0) ts[tt] = red[0];
        __syncthreads();
    }
    if (tid < 16) {
        float blk = 0.f;
        for (int c = 0; c < 128; c++) blk += tn_wb[tid * 256 + c] * e1s[c];
        for (int c = 0; c < 128; c++) blk += tn_wb[tid * 256 + 128 + c] * e2s[c];
        float v = ts[tid] + blk + tn_bias[tid];
        ts[tid] = v > 0.f ? v : 0.f;
    }
    __syncthreads();
    if (tid < 16) {
        float h = fc1_b[tid];
        for (int u2 = 0; u2 < 16; u2++) h += fc1_w[tid * 16 + u2] * ts[u2];
        hs[tid] = h > 0.f ? h : 0.f;
    }
    __syncthreads();
    if (tid == 0) {
        float z = sc_b[0];
        for (int u2 = 0; u2 < 16; u2++) z += sc_w[u2] * hs[u2];
        out[b] = 1.0f / (1.0f + expf(-z));
    }
}

// ------------------------------------------------------------------ host
template <typename T>
static float* symaddr(T& sym_) {
    void* p = nullptr;
    cudaGetSymbolAddress(&p, sym_);
    return (float*)p;
}

extern "C" void kernel_launch(void* const* d_in, const int* in_sizes, int n_in,
                              void* d_out, int out_size) {
    (void)in_sizes; (void)n_in; (void)out_size;
    const float* f1    = (const float*)d_in[0];
    const float* f2    = (const float*)d_in[1];
    const float* sw1   = (const float*)d_in[2];
    const float* sg1   = (const float*)d_in[3];
    const float* sb1   = (const float*)d_in[4];
    const float* fw1   = (const float*)d_in[5];
    const float* fg1   = (const float*)d_in[6];
    const float* fb1   = (const float*)d_in[7];
    const float* sw2   = (const float*)d_in[8];
    const float* sg2   = (const float*)d_in[9];
    const float* sb2   = (const float*)d_in[10];
    const float* fw2   = (const float*)d_in[11];
    const float* fg2   = (const float*)d_in[12];
    const float* fb2   = (const float*)d_in[13];
    const float* sw3   = (const float*)d_in[14];
    const float* sg3   = (const float*)d_in[15];
    const float* sb3   = (const float*)d_in[16];
    const float* fw3   = (const float*)d_in[17];
    const float* fg3   = (const float*)d_in[18];
    const float* fb3   = (const float*)d_in[19];
    const float* ew    = (const float*)d_in[20];
    const float* eg    = (const float*)d_in[21];
    const float* ebv   = (const float*)d_in[22];
    const float* att_w = (const float*)d_in[23];
    const float* tn_w  = (const float*)d_in[24];
    const float* tn_wb = (const float*)d_in[25];
    const float* tn_b  = (const float*)d_in[26];
    const float* fc1_w = (const float*)d_in[27];
    const float* fc1_b = (const float*)d_in[28];
    const float* sc_w  = (const float*)d_in[29];
    const float* sc_b  = (const float*)d_in[30];
    float* out = (float*)d_out;

    float* negp  = symaddr(g_neg);
    int*   idxp  = (int*)symaddr(g_idx);
    float* xxp   = symaddr(g_xx);
    float* x0p   = symaddr(g_x0);
    float* s0p   = symaddr(g_s0);
    float* h1p   = symaddr(g_h1);
    float* h2p   = symaddr(g_h2);
    float* h3p   = symaddr(g_h3);
    float* t1p   = symaddr(g_t1);
    float* t2p   = symaddr(g_t2);
    float* t3p   = symaddr(g_t3);
    float* embp  = symaddr(g_emb);
    float* esump = symaddr(g_esum);
    float* gcp   = symaddr(g_gc);
    float* e1p   = symaddr(g_e1);
    float* e2p   = symaddr(g_e2);

    // dynamic smem sizes
    const int SM_C1 = (2*3*64   + 8*21*8  ) * 4 + 8*KNN*4;   // conv<3,4,64,8>
    const int SM_C2 = (2*64*64  + 8*21*68 ) * 4 + 8*KNN*4;   // conv<64,64,64,8>
    const int SM_C3 = (2*64*128 + 4*21*68 ) * 4 + 4*KNN*4;   // conv<64,64,128,4>
    const int SM_C4 = (2*128*64 + 8*21*132) * 4 + 8*KNN*4;   // conv<128,128,64,8>
    const int SM_EW = (256*128 + 4*256) * 4;

    cudaFuncSetAttribute(conv_kernel<64,64,64,8>,   cudaFuncAttributeMaxDynamicSharedMemorySize, SM_C2);
    cudaFuncSetAttribute(conv_kernel<64,64,128,4>,  cudaFuncAttributeMaxDynamicSharedMemorySize, SM_C3);
    cudaFuncSetAttribute(conv_kernel<128,128,64,8>, cudaFuncAttributeMaxDynamicSharedMemorySize, SM_C4);
    cudaFuncSetAttribute(emb_kernel,                cudaFuncAttributeMaxDynamicSharedMemorySize, SM_EW);

    for (int set = 0; set < 2; set++) {
        const float* fin = set ? f2 : f1;
        transpose_kernel<<<(BB*NPT*132 + 255) / 256, 256>>>(fin, x0p, s0p);

        // xyz chain: 3 -> 64 -> 64 -> 128
        xx_kernel<4><<<NROW/256, 256>>>(x0p, xxp);
        dist_kernel<4><<<dim3(32,32,BB), 256>>>(x0p, xxp, negp);
        topk_kernel<<<NROW, 256>>>(negp, idxp);
        conv_kernel<3,4,64,8><<<BB*NPT/8, 128, SM_C1>>>(x0p, idxp, sw1, sg1, sb1, h1p);

        xx_kernel<64><<<NROW/256, 256>>>(h1p, xxp);
        dist_kernel<64><<<dim3(32,32,BB), 256>>>(h1p, xxp, negp);
        topk_kernel<<<NROW, 256>>>(negp, idxp);
        conv_kernel<64,64,64,8><<<BB*NPT/8, 128, SM_C2>>>(h1p, idxp, sw2, sg2, sb2, h2p);

        xx_kernel<64><<<NROW/256, 256>>>(h2p, xxp);
        dist_kernel<64><<<dim3(32,32,BB), 256>>>(h2p, xxp, negp);
        topk_kernel<<<NROW, 256>>>(negp, idxp);
        conv_kernel<64,64,128,4><<<BB*NPT/4, 128, SM_C3>>>(h2p, idxp, sw3, sg3, sb3, h3p);

        // sem chain: 128 -> 64 -> 64 -> 128
        xx_kernel<128><<<NROW/256, 256>>>(s0p, xxp);
        dist_kernel<128><<<dim3(32,32,BB), 256>>>(s0p, xxp, negp);
        topk_kernel<<<NROW, 256>>>(negp, idxp);
        conv_kernel<128,128,64,8><<<BB*NPT/8, 128, SM_C4>>>(s0p, idxp, fw1, fg1, fb1, t1p);

        xx_kernel<64><<<NROW/256, 256>>>(t1p, xxp);
        dist_kernel<64><<<dim3(32,32,BB), 256>>>(t1p, xxp, negp);
        topk_kernel<<<NROW, 256>>>(negp, idxp);
        conv_kernel<64,64,64,8><<<BB*NPT/8, 128, SM_C2>>>(t1p, idxp, fw2, fg2, fb2, t2p);

        xx_kernel<64><<<NROW/256, 256>>>(t2p, xxp);
        dist_kernel<64><<<dim3(32,32,BB), 256>>>(t2p, xxp, negp);
        topk_kernel<<<NROW, 256>>>(negp, idxp);
        conv_kernel<64,64,128,4><<<BB*NPT/4, 128, SM_C3>>>(t2p, idxp, fw3, fg3, fb3, t3p);

        // fuse + attention for this set
        emb_kernel<<<NROW/32, 128, SM_EW>>>(h3p, t3p, ew, eg, ebv, embp);

        float* att_out = out + 8 + set * (BB * NPT);
        float* epooled = set ? e2p : e1p;
        colsum_kernel<<<BB, 128>>>(embp, esump);
        gc_kernel<<<BB, 128>>>(esump, att_w, gcp);
        sc_kernel<<<NROW/4, 128>>>(embp, gcp, att_out);
        pool_kernel<<<BB, 128>>>(embp, att_out, epooled);
    }

    final_kernel<<<BB, 128>>>(e1p, e2p, tn_w, tn_wb, tn_b, fc1_w, fc1_b, sc_w, sc_b, out);
}

// round 4
// speedup vs baseline: 1.4811x; 1.4811x over previous
#include <cuda_runtime.h>
#include <math.h>
#include <stdint.h>

#define BB   8
#define NPT  1024
#define KNN  20
#define NROW (BB*NPT)

// ------------------------------------------------------------------ scratch
__device__ float g_neg[NROW*NPT];      // 32 MB distance matrix (per edge block, reused)
__device__ int   g_idx[NROW*KNN];
__device__ float g_xx [NROW];
__device__ float g_x0 [NROW*4];        // xyz, padded to 4 (4th = 0)
__device__ float g_s0 [NROW*128];      // sem
__device__ float g_h1 [NROW*64];
__device__ float g_h2 [NROW*64];
__device__ float g_h3 [NROW*128];
__device__ float g_t1 [NROW*64];
__device__ float g_t2 [NROW*64];
__device__ float g_t3 [NROW*128];
__device__ float g_emb[NROW*128];      // reused per set
__device__ float g_part[BB*8*128];
__device__ float g_gc  [BB*128];
__device__ float g_e1  [BB*128];
__device__ float g_e2  [BB*128];

// ------------------------------------------------------------------ transpose input (B,C,N) -> point-major (coalesced reads)
__global__ void transpose_kernel(const float* __restrict__ in, float* __restrict__ x0, float* __restrict__ s0) {
    int j = blockIdx.x * blockDim.x + threadIdx.x;
    int total = BB * 131 * NPT;
    if (j >= total) return;
    int n = j % NPT;
    int c = (j / NPT) % 131;
    int b = j / (131 * NPT);
    float v = in[j];
    if (c < 3) {
        x0[(b*NPT + n)*4 + c] = v;
        if (c == 0) x0[(b*NPT + n)*4 + 3] = 0.0f;
    } else {
        s0[(b*NPT + n)*128 + (c - 3)] = v;
    }
}

// ------------------------------------------------------------------ per-point squared norm
template <int CROW>
__global__ void xx_kernel(const float* __restrict__ X, float* __restrict__ xx) {
    int j = blockIdx.x * 256 + threadIdx.x;
    if (j >= NROW) return;
    const float* r = X + (long)j * CROW;
    float a = 0.f;
    #pragma unroll
    for (int c = 0; c < CROW; c++) a += r[c] * r[c];
    xx[j] = a;
}

// ------------------------------------------------------------------ neg distance matrix: 2*X.X^T - xx_n - xx_m
// 64x64 tile, 256 threads, 4x4 register micro-tile
template <int CROW>
__global__ __launch_bounds__(256) void dist_kernel(const float* __restrict__ X,
                                                   const float* __restrict__ xx,
                                                   float* __restrict__ neg) {
    constexpr int TC = (CROW < 16) ? CROW : 16;
    __shared__ float As[TC][64];
    __shared__ float Bs[TC][64];
    int b = blockIdx.z;
    int row0 = blockIdx.y * 64;
    int col0 = blockIdx.x * 64;
    int t = threadIdx.x;
    int tx = t & 15, ty = t >> 4;
    float acc[4][4];
    #pragma unroll
    for (int i = 0; i < 4; i++)
        #pragma unroll
        for (int j = 0; j < 4; j++) acc[i][j] = 0.f;

    for (int c0 = 0; c0 < CROW; c0 += TC) {
        constexpr int NLD = (64 * TC + 255) / 256;
        #pragma unroll
        for (int l = 0; l < NLD; l++) {
            int i = t + l * 256;
            if ((64 * TC) % 256 == 0 || i < 64 * TC) {
                int r = i / TC, c = i % TC;
                As[c][r] = X[((long)(b*NPT) + row0 + r) * CROW + c0 + c];
                Bs[c][r] = X[((long)(b*NPT) + col0 + r) * CROW + c0 + c];
            }
        }
        __syncthreads();
        #pragma unroll
        for (int c = 0; c < TC; c++) {
            float4 av = *(const float4*)&As[c][ty * 4];
            float4 bv = *(const float4*)&Bs[c][tx * 4];
            float aa[4] = {av.x, av.y, av.z, av.w};
            float bb2[4] = {bv.x, bv.y, bv.z, bv.w};
            #pragma unroll
            for (int i = 0; i < 4; i++)
                #pragma unroll
                for (int j = 0; j < 4; j++) acc[i][j] += aa[i] * bb2[j];
        }
        __syncthreads();
    }
    float xr[4], xc[4];
    #pragma unroll
    for (int i = 0; i < 4; i++) {
        xr[i] = xx[b*NPT + row0 + ty*4 + i];
        xc[i] = xx[b*NPT + col0 + tx*4 + i];
    }
    #pragma unroll
    for (int i = 0; i < 4; i++) {
        float4 o;
        o.x = 2.f*acc[i][0] - xr[i] - xc[0];
        o.y = 2.f*acc[i][1] - xr[i] - xc[1];
        o.z = 2.f*acc[i][2] - xr[i] - xc[2];
        o.w = 2.f*acc[i][3] - xr[i] - xc[3];
        *(float4*)&neg[((long)(b*NPT) + row0 + ty*4 + i) * NPT + col0 + tx*4] = o;
    }
}

// ------------------------------------------------------------------ top-20: warp per row, register-resident argmax tournament
// Downstream is max over k -> index ORDER is irrelevant; set + lax tie-break preserved.
__global__ __launch_bounds__(256) void topk_kernel(const float* __restrict__ neg, int* __restrict__ idxout) {
    int warp = threadIdx.x >> 5, lane = threadIdx.x & 31;
    int row = blockIdx.x * 8 + warp;
    const float* rp = neg + (long)row * NPT;

    unsigned key[32];
    #pragma unroll
    for (int j = 0; j < 32; j++) {
        unsigned u = __float_as_uint(rp[lane + 32 * j]);
        key[j] = (u & 0x80000000u) ? ~u : (u | 0x80000000u);  // order-preserving; 0 < all real keys
    }
    // local argmax (strict > keeps smallest j => smallest index within lane)
    unsigned bk = key[0]; int bj = 0;
    #pragma unroll
    for (int j = 1; j < 32; j++) if (key[j] > bk) { bk = key[j]; bj = j; }

    for (int sel = 0; sel < KNN; sel++) {
        unsigned wk = bk;
        int widx = lane + 32 * bj;
        #pragma unroll
        for (int off = 16; off; off >>= 1) {
            unsigned ok = __shfl_down_sync(0xffffffffu, wk, off);
            int      oi = __shfl_down_sync(0xffffffffu, widx, off);
            if (ok > wk || (ok == wk && oi < widx)) { wk = ok; widx = oi; }
        }
        widx = __shfl_sync(0xffffffffu, widx, 0);
        if (lane == 0) idxout[row * KNN + sel] = widx;
        if ((widx & 31) == lane) {
            int jb = widx >> 5;
            #pragma unroll
            for (int j = 0; j < 32; j++) if (j == jb) key[j] = 0u;
            bk = key[0]; bj = 0;
            #pragma unroll
            for (int j = 1; j < 32; j++) if (key[j] > bk) { bk = key[j]; bj = j; }
        }
    }
}

// ------------------------------------------------------------------ fused gather + edge conv + BN + leaky + max_k
template <int CIN, int CROW, int COUT, int P>
__global__ __launch_bounds__(128)
void conv_kernel(const float* __restrict__ X, const int* __restrict__ idx,
                 const float* __restrict__ w, const float* __restrict__ gam,
                 const float* __restrict__ bet, float* __restrict__ out) {
    constexpr int TPP = COUT / 4;
    constexpr int CP  = CROW + 4;
    extern __shared__ float sm[];
    float* wt = sm;                          // [CIN][COUT]  (w1 transposed)
    float* wd = wt + CIN * COUT;             // [CIN][COUT]  (w2-w1 transposed)
    float* nb = wd + CIN * COUT;             // [P][21][CP]  (20 neighbors + ctr)
    int* sidx = (int*)(nb + P * 21 * CP);    // [P][KNN]

    int t = threadIdx.x;
    int b  = blockIdx.x / (NPT / P);
    int n0 = (blockIdx.x % (NPT / P)) * P;

    for (int i = t; i < CIN * COUT; i += 128) {
        int c = i / COUT, o = i % COUT;
        float w1 = w[o * (2*CIN) + c];
        wt[c * COUT + o] = w1;
        wd[c * COUT + o] = w[o * (2*CIN) + CIN + c] - w1;
    }
    for (int i = t; i < P * KNN; i += 128)
        sidx[i] = idx[((long)(b*NPT) + n0) * KNN + i];
    __syncthreads();

    constexpr int V4 = CROW / 4;
    for (int i = t; i < P * 21 * V4; i += 128) {
        int c4 = i % V4;
        int vec = i / V4;
        int p = vec / 21, k = vec % 21;
        int m = (k < KNN) ? sidx[p*KNN + k] : (n0 + p);
        float4 v = *(const float4*)&X[((long)(b*NPT) + m) * CROW + 4*c4];
        *(float4*)&nb[(p*21 + k) * CP + 4*c4] = v;
    }
    __syncthreads();

    int p  = t / TPP;
    int o4 = (t % TPP) * 4;
    float4 s[KNN];
    float4 u = make_float4(0.f, 0.f, 0.f, 0.f);
    #pragma unroll
    for (int k = 0; k < KNN; k++) s[k] = make_float4(0.f, 0.f, 0.f, 0.f);

    const float* nbp = nb + p * 21 * CP;
    for (int c = 0; c < CIN; c++) {
        float4 w4  = *(const float4*)&wt[c * COUT + o4];
        float4 wd4 = *(const float4*)&wd[c * COUT + o4];
        float ct = nbp[20 * CP + c];
        u.x += wd4.x * ct; u.y += wd4.y * ct; u.z += wd4.z * ct; u.w += wd4.w * ct;
        #pragma unroll
        for (int k = 0; k < KNN; k++) {
            float nv = nbp[k * CP + c];
            s[k].x += w4.x * nv; s[k].y += w4.y * nv;
            s[k].z += w4.z * nv; s[k].w += w4.w * nv;
        }
    }
    float4 mx = s[0], mn = s[0];
    #pragma unroll
    for (int k = 1; k < KNN; k++) {
        mx.x = fmaxf(mx.x, s[k].x); mx.y = fmaxf(mx.y, s[k].y);
        mx.z = fmaxf(mx.z, s[k].z); mx.w = fmaxf(mx.w, s[k].w);
        mn.x = fminf(mn.x, s[k].x); mn.y = fminf(mn.y, s[k].y);
        mn.z = fminf(mn.z, s[k].z); mn.w = fminf(mn.w, s[k].w);
    }
    float inv = rsqrtf(1.0f + 1e-5f);
    float4 gmv = *(const float4*)&gam[o4];
    float4 btv = *(const float4*)&bet[o4];
    float4 res;
    { float a = gmv.x*inv; float base = ((a>=0.f)?mx.x:mn.x) + u.x; float v = a*base + btv.x; res.x = v>=0.f?v:0.2f*v; }
    { float a = gmv.y*inv; float base = ((a>=0.f)?mx.y:mn.y) + u.y; float v = a*base + btv.y; res.y = v>=0.f?v:0.2f*v; }
    { float a = gmv.z*inv; float base = ((a>=0.f)?mx.z:mn.z) + u.z; float v = a*base + btv.z; res.z = v>=0.f?v:0.2f*v; }
    { float a = gmv.w*inv; float base = ((a>=0.f)?mx.w:mn.w) + u.w; float v = a*base + btv.w; res.w = v>=0.f?v:0.2f*v; }
    int n = n0 + p;
    *(float4*)&out[((long)(b*NPT) + n) * COUT + o4] = res;
}

// ------------------------------------------------------------------ ew conv on concat(H3,S3) -> emb (B*N,128)
__global__ __launch_bounds__(128)
void emb_kernel(const float* __restrict__ H3, const float* __restrict__ S3,
                const float* __restrict__ ew, const float* __restrict__ eg,
                const float* __restrict__ eb, float* __restrict__ emb) {
    extern __shared__ float sm[];
    float* wts  = sm;                 // [256][128]
    float* rows = wts + 256 * 128;    // [4][256]
    int t = threadIdx.x;
    for (int i = t; i < 256 * 128; i += 128) {
        int c = i / 128, o = i % 128;
        wts[c * 128 + o] = ew[o * 256 + c];
    }
    const int NITER = 8;
    int base = blockIdx.x * (4 * NITER);
    int pl = t / 32;
    int o4 = (t % 32) * 4;
    float inv = rsqrtf(1.0f + 1e-5f);
    for (int it = 0; it < NITER; it++) {
        __syncthreads();
        int p0 = base + it * 4;
        for (int i = t; i < 4 * 256; i += 128) {
            int pp = i / 256, c = i % 256;
            long pt = p0 + pp;
            rows[pp * 256 + c] = (c < 128) ? H3[pt * 128 + c] : S3[pt * 128 + c - 128];
        }
        __syncthreads();
        float4 acc = make_float4(0.f, 0.f, 0.f, 0.f);
        for (int c = 0; c < 256; c++) {
            float4 w4 = *(const float4*)&wts[c * 128 + o4];
            float xv = rows[pl * 256 + c];
            acc.x += w4.x * xv; acc.y += w4.y * xv;
            acc.z += w4.z * xv; acc.w += w4.w * xv;
        }
        float4 gmv = *(const float4*)&eg[o4];
        float4 btv = *(const float4*)&eb[o4];
        float4 r;
        { float v = gmv.x*inv*acc.x + btv.x; r.x = v>=0.f?v:0.2f*v; }
        { float v = gmv.y*inv*acc.y + btv.y; r.y = v>=0.f?v:0.2f*v; }
        { float v = gmv.z*inv*acc.z + btv.z; r.z = v>=0.f?v:0.2f*v; }
        { float v = gmv.w*inv*acc.w + btv.w; r.w = v>=0.f?v:0.2f*v; }
        long pt = p0 + pl;
        *(float4*)&emb[pt * 128 + o4] = r;
    }
}

// ------------------------------------------------------------------ attention pieces (two-stage reductions)
__global__ void colsum_part(const float* __restrict__ emb, float* __restrict__ part) {
    int b = blockIdx.x, seg = blockIdx.y, f = threadIdx.x;
    const float* p = emb + ((long)(b*NPT) + seg*128) * 128 + f;
    float a = 0.f;
    #pragma unroll 4
    for (int n = 0; n < 128; n++) a += p[n * 128];
    part[(b*8 + seg) * 128 + f] = a;
}

__global__ void gc2_kernel(const float* __restrict__ part, const float* __restrict__ att_w,
                           float* __restrict__ gc) {
    __shared__ float es[128];
    int b = blockIdx.x, t = threadIdx.x;
    float a = 0.f;
    #pragma unroll
    for (int s = 0; s < 8; s++) a += part[(b*8 + s) * 128 + t];
    es[t] = a;
    __syncthreads();
    float gv = 0.f;
    for (int f = 0; f < 128; f++) gv += es[f] * att_w[f * 128 + t];
    gc[b * 128 + t] = tanhf(gv * (1.0f / NPT));
}

__global__ void sc_kernel(const float* __restrict__ emb, const float* __restrict__ gc,
                          float* __restrict__ att) {
    int warp = threadIdx.x >> 5, lane = threadIdx.x & 31;
    int pid = blockIdx.x * 4 + warp;
    int b = pid >> 10;
    float a = 0.f;
    #pragma unroll
    for (int j = 0; j < 4; j++) {
        int f = lane + 32 * j;
        a += emb[(long)pid * 128 + f] * gc[b * 128 + f];
    }
    #pragma unroll
    for (int off = 16; off; off >>= 1) a += __shfl_down_sync(0xffffffffu, a, off);
    if (lane == 0) att[pid] = 1.0f / (1.0f + expf(-a));
}

__global__ void pool_part(const float* __restrict__ emb, const float* __restrict__ att,
                          float* __restrict__ part) {
    int b = blockIdx.x, seg = blockIdx.y, f = threadIdx.x;
    const float* p = emb + ((long)(b*NPT) + seg*128) * 128 + f;
    const float* aw = att + b*NPT + seg*128;
    float a = 0.f;
    #pragma unroll 4
    for (int n = 0; n < 128; n++) a += p[n * 128] * aw[n];
    part[(b*8 + seg) * 128 + f] = a;
}

__global__ void pool_fin(const float* __restrict__ part, float* __restrict__ e) {
    int b = blockIdx.x, t = threadIdx.x;
    float a = 0.f;
    #pragma unroll
    for (int s = 0; s < 8; s++) a += part[(b*8 + s) * 128 + t];
    e[b * 128 + t] = a;
}

// ------------------------------------------------------------------ final scoring
__global__ void final_kernel(const float* __restrict__ e1, const float* __restrict__ e2,
                             const float* __restrict__ tn_w, const float* __restrict__ tn_wb,
                             const float* __restrict__ tn_bias, const float* __restrict__ fc1_w,
                             const float* __restrict__ fc1_b, const float* __restrict__ sc_w,
                             const float* __restrict__ sc_b, float* __restrict__ out) {
    __shared__ float e1s[128], e2s[128], red[128], ts[16], hs[16];
    int b = blockIdx.x, tid = threadIdx.x;
    e1s[tid] = e1[b * 128 + tid];
    e2s[tid] = e2[b * 128 + tid];
    __syncthreads();
    for (int tt = 0; tt < 16; tt++) {
        float inner = 0.f;
        const float* wrow = tn_w + (long)tid * 128 * 16 + tt;
        for (int gI = 0; gI < 128; gI++) inner += wrow[gI * 16] * e2s[gI];
        red[tid] = e1s[tid] * inner;
        __syncthreads();
        for (int s2 = 64; s2; s2 >>= 1) {
            if (tid < s2) red[tid] += red[tid + s2];
            __syncthreads();
        }
        if (tid == 0) ts[tt] = red[0];
        __syncthreads();
    }
    if (tid < 16) {
        float blk = 0.f;
        for (int c = 0; c < 128; c++) blk += tn_wb[tid * 256 + c] * e1s[c];
        for (int c = 0; c < 128; c++) blk += tn_wb[tid * 256 + 128 + c] * e2s[c];
        float v = ts[tid] + blk + tn_bias[tid];
        ts[tid] = v > 0.f ? v : 0.f;
    }
    __syncthreads();
    if (tid < 16) {
        float h = fc1_b[tid];
        for (int u2 = 0; u2 < 16; u2++) h += fc1_w[tid * 16 + u2] * ts[u2];
        hs[tid] = h > 0.f ? h : 0.f;
    }
    __syncthreads();
    if (tid == 0) {
        float z = sc_b[0];
        for (int u2 = 0; u2 < 16; u2++) z += sc_w[u2] * hs[u2];
        out[b] = 1.0f / (1.0f + expf(-z));
    }
}

// ------------------------------------------------------------------ host
template <typename T>
static float* symaddr(T& sym_) {
    void* p = nullptr;
    cudaGetSymbolAddress(&p, sym_);
    return (float*)p;
}

extern "C" void kernel_launch(void* const* d_in, const int* in_sizes, int n_in,
                              void* d_out, int out_size) {
    (void)in_sizes; (void)n_in; (void)out_size;
    const float* f1    = (const float*)d_in[0];
    const float* f2    = (const float*)d_in[1];
    const float* sw1   = (const float*)d_in[2];
    const float* sg1   = (const float*)d_in[3];
    const float* sb1   = (const float*)d_in[4];
    const float* fw1   = (const float*)d_in[5];
    const float* fg1   = (const float*)d_in[6];
    const float* fb1   = (const float*)d_in[7];
    const float* sw2   = (const float*)d_in[8];
    const float* sg2   = (const float*)d_in[9];
    const float* sb2   = (const float*)d_in[10];
    const float* fw2   = (const float*)d_in[11];
    const float* fg2   = (const float*)d_in[12];
    const float* fb2   = (const float*)d_in[13];
    const float* sw3   = (const float*)d_in[14];
    const float* sg3   = (const float*)d_in[15];
    const float* sb3   = (const float*)d_in[16];
    const float* fw3   = (const float*)d_in[17];
    const float* fg3   = (const float*)d_in[18];
    const float* fb3   = (const float*)d_in[19];
    const float* ew    = (const float*)d_in[20];
    const float* eg    = (const float*)d_in[21];
    const float* ebv   = (const float*)d_in[22];
    const float* att_w = (const float*)d_in[23];
    const float* tn_w  = (const float*)d_in[24];
    const float* tn_wb = (const float*)d_in[25];
    const float* tn_b  = (const float*)d_in[26];
    const float* fc1_w = (const float*)d_in[27];
    const float* fc1_b = (const float*)d_in[28];
    const float* sc_w  = (const float*)d_in[29];
    const float* sc_b  = (const float*)d_in[30];
    float* out = (float*)d_out;

    float* negp  = symaddr(g_neg);
    int*   idxp  = (int*)symaddr(g_idx);
    float* xxp   = symaddr(g_xx);
    float* x0p   = symaddr(g_x0);
    float* s0p   = symaddr(g_s0);
    float* h1p   = symaddr(g_h1);
    float* h2p   = symaddr(g_h2);
    float* h3p   = symaddr(g_h3);
    float* t1p   = symaddr(g_t1);
    float* t2p   = symaddr(g_t2);
    float* t3p   = symaddr(g_t3);
    float* embp  = symaddr(g_emb);
    float* partp = symaddr(g_part);
    float* gcp   = symaddr(g_gc);
    float* e1p   = symaddr(g_e1);
    float* e2p   = symaddr(g_e2);

    const int SM_C1 = (2*3*64   + 8*21*8  ) * 4 + 8*KNN*4;   // conv<3,4,64,8>
    const int SM_C2 = (2*64*64  + 8*21*68 ) * 4 + 8*KNN*4;   // conv<64,64,64,8>
    const int SM_C3 = (2*64*128 + 4*21*68 ) * 4 + 4*KNN*4;   // conv<64,64,128,4>
    const int SM_C4 = (2*128*64 + 8*21*132) * 4 + 8*KNN*4;   // conv<128,128,64,8>
    const int SM_EW = (256*128 + 4*256) * 4;

    cudaFuncSetAttribute(conv_kernel<64,64,64,8>,   cudaFuncAttributeMaxDynamicSharedMemorySize, SM_C2);
    cudaFuncSetAttribute(conv_kernel<64,64,128,4>,  cudaFuncAttributeMaxDynamicSharedMemorySize, SM_C3);
    cudaFuncSetAttribute(conv_kernel<128,128,64,8>, cudaFuncAttributeMaxDynamicSharedMemorySize, SM_C4);
    cudaFuncSetAttribute(emb_kernel,                cudaFuncAttributeMaxDynamicSharedMemorySize, SM_EW);

    for (int set = 0; set < 2; set++) {
        const float* fin = set ? f2 : f1;
        transpose_kernel<<<(BB*131*NPT + 255) / 256, 256>>>(fin, x0p, s0p);

        // xyz chain: 3 -> 64 -> 64 -> 128
        xx_kernel<4><<<NROW/256, 256>>>(x0p, xxp);
        dist_kernel<4><<<dim3(16,16,BB), 256>>>(x0p, xxp, negp);
        topk_kernel<<<NROW/8, 256>>>(negp, idxp);
        conv_kernel<3,4,64,8><<<BB*NPT/8, 128, SM_C1>>>(x0p, idxp, sw1, sg1, sb1, h1p);

        xx_kernel<64><<<NROW/256, 256>>>(h1p, xxp);
        dist_kernel<64><<<dim3(16,16,BB), 256>>>(h1p, xxp, negp);
        topk_kernel<<<NROW/8, 256>>>(negp, idxp);
        conv_kernel<64,64,64,8><<<BB*NPT/8, 128, SM_C2>>>(h1p, idxp, sw2, sg2, sb2, h2p);

        xx_kernel<64><<<NROW/256, 256>>>(h2p, xxp);
        dist_kernel<64><<<dim3(16,16,BB), 256>>>(h2p, xxp, negp);
        topk_kernel<<<NROW/8, 256>>>(negp, idxp);
        conv_kernel<64,64,128,4><<<BB*NPT/4, 128, SM_C3>>>(h2p, idxp, sw3, sg3, sb3, h3p);

        // sem chain: 128 -> 64 -> 64 -> 128
        xx_kernel<128><<<NROW/256, 256>>>(s0p, xxp);
        dist_kernel<128><<<dim3(16,16,BB), 256>>>(s0p, xxp, negp);
        topk_kernel<<<NROW/8, 256>>>(negp, idxp);
        conv_kernel<128,128,64,8><<<BB*NPT/8, 128, SM_C4>>>(s0p, idxp, fw1, fg1, fb1, t1p);

        xx_kernel<64><<<NROW/256, 256>>>(t1p, xxp);
        dist_kernel<64><<<dim3(16,16,BB), 256>>>(t1p, xxp, negp);
        topk_kernel<<<NROW/8, 256>>>(negp, idxp);
        conv_kernel<64,64,64,8><<<BB*NPT/8, 128, SM_C2>>>(t1p, idxp, fw2, fg2, fb2, t2p);

        xx_kernel<64><<<NROW/256, 256>>>(t2p, xxp);
        dist_kernel<64><<<dim3(16,16,BB), 256>>>(t2p, xxp, negp);
        topk_kernel<<<NROW/8, 256>>>(negp, idxp);
        conv_kernel<64,64,128,4><<<BB*NPT/4, 128, SM_C3>>>(t2p, idxp, fw3, fg3, fb3, t3p);

        // fuse + attention for this set
        emb_kernel<<<NROW/32, 128, SM_EW>>>(h3p, t3p, ew, eg, ebv, embp);

        float* att_out = out + 8 + set * (BB * NPT);
        float* epooled = set ? e2p : e1p;
        colsum_part<<<dim3(BB, 8), 128>>>(embp, partp);
        gc2_kernel<<<BB, 128>>>(partp, att_w, gcp);
        sc_kernel<<<NROW/4, 128>>>(embp, gcp, att_out);
        pool_part<<<dim3(BB, 8), 128>>>(embp, att_out, partp);
        pool_fin<<<BB, 128>>>(partp, epooled);
    }

    final_kernel<<<BB, 128>>>(e1p, e2p, tn_w, tn_wb, tn_b, fc1_w, fc1_b, sc_w, sc_b, out);
}

// round 5
// speedup vs baseline: 1.9239x; 1.2990x over previous
#include <cuda_runtime.h>
#include <math.h>
#include <stdint.h>

#define BB   8
#define NB   16          // both graphs merged into one batch
#define NPT  1024
#define KNN  20
#define NROW (NB*NPT)    // 16384

// ------------------------------------------------------------------ scratch
__device__ float g_neg[NROW*NPT];      // 64 MB distance matrix (reused)
__device__ int   g_idx[NROW*KNN];
__device__ float g_xx [NROW];
__device__ float g_x0 [NROW*4];
__device__ float g_s0 [NROW*128];
__device__ float g_h1 [NROW*64];
__device__ float g_h2 [NROW*64];
__device__ float g_h3 [NROW*128];
__device__ float g_emb[NROW*128];
__device__ float g_part[NB*8*128];
__device__ float g_gc  [NB*128];
__device__ float g_e   [NB*128];

// ------------------------------------------------------------------ transpose both inputs (B,C,N) -> point-major
__global__ void transpose_kernel(const float* __restrict__ f1, const float* __restrict__ f2,
                                 float* __restrict__ x0, float* __restrict__ s0) {
    int j = blockIdx.x * blockDim.x + threadIdx.x;
    int total = NB * 131 * NPT;
    if (j >= total) return;
    int n = j % NPT;
    int c = (j / NPT) % 131;
    int b = j / (131 * NPT);
    const float* in = (b < BB) ? f1 : f2;
    float v = in[((long)(b & 7) * 131 + c) * NPT + n];
    if (c < 3) {
        x0[(b*NPT + n)*4 + c] = v;
        if (c == 0) x0[(b*NPT + n)*4 + 3] = 0.0f;
    } else {
        s0[((long)(b*NPT) + n)*128 + (c - 3)] = v;
    }
}

// ------------------------------------------------------------------ per-point squared norm
template <int CROW>
__global__ void xx_kernel(const float* __restrict__ X, float* __restrict__ xx) {
    int j = blockIdx.x * 256 + threadIdx.x;
    if (j >= NROW) return;
    const float* r = X + (long)j * CROW;
    float a = 0.f;
    #pragma unroll
    for (int c = 0; c < CROW; c++) a += r[c] * r[c];
    xx[j] = a;
}

// ------------------------------------------------------------------ neg distance: 2*X.X^T - xx_n - xx_m
// 128x128 tile, 256 threads, 8x8 register micro-tile
template <int CROW>
__global__ __launch_bounds__(256) void dist_kernel(const float* __restrict__ X,
                                                   const float* __restrict__ xx,
                                                   float* __restrict__ neg) {
    constexpr int TC = (CROW < 16) ? CROW : 16;
    constexpr int LDW = 132;                  // padded row to dodge bank conflicts
    __shared__ float As[TC][LDW];
    __shared__ float Bs[TC][LDW];
    int b = blockIdx.z;
    int row0 = blockIdx.y * 128;
    int col0 = blockIdx.x * 128;
    int t = threadIdx.x;
    int tx = t & 15, ty = t >> 4;
    float acc[8][8];
    #pragma unroll
    for (int i = 0; i < 8; i++)
        #pragma unroll
        for (int j = 0; j < 8; j++) acc[i][j] = 0.f;

    for (int c0 = 0; c0 < CROW; c0 += TC) {
        constexpr int NLD = (128 * TC) / 256;
        #pragma unroll
        for (int l = 0; l < NLD; l++) {
            int i = t + l * 256;
            int r = i / TC, c = i % TC;
            As[c][r] = X[((long)(b*NPT) + row0 + r) * CROW + c0 + c];
            Bs[c][r] = X[((long)(b*NPT) + col0 + r) * CROW + c0 + c];
        }
        __syncthreads();
        #pragma unroll
        for (int c = 0; c < TC; c++) {
            float4 a0 = *(const float4*)&As[c][ty*8];
            float4 a1 = *(const float4*)&As[c][ty*8+4];
            float4 b0 = *(const float4*)&Bs[c][tx*8];
            float4 b1 = *(const float4*)&Bs[c][tx*8+4];
            float aa[8] = {a0.x,a0.y,a0.z,a0.w,a1.x,a1.y,a1.z,a1.w};
            float bb2[8] = {b0.x,b0.y,b0.z,b0.w,b1.x,b1.y,b1.z,b1.w};
            #pragma unroll
            for (int i = 0; i < 8; i++)
                #pragma unroll
                for (int j = 0; j < 8; j++) acc[i][j] += aa[i] * bb2[j];
        }
        __syncthreads();
    }
    float xr[8], xc[8];
    #pragma unroll
    for (int i = 0; i < 8; i++) {
        xr[i] = xx[b*NPT + row0 + ty*8 + i];
        xc[i] = xx[b*NPT + col0 + tx*8 + i];
    }
    #pragma unroll
    for (int i = 0; i < 8; i++) {
        long rbase = ((long)(b*NPT) + row0 + ty*8 + i) * NPT + col0 + tx*8;
        float4 o0, o1;
        o0.x = 2.f*acc[i][0] - xr[i] - xc[0];
        o0.y = 2.f*acc[i][1] - xr[i] - xc[1];
        o0.z = 2.f*acc[i][2] - xr[i] - xc[2];
        o0.w = 2.f*acc[i][3] - xr[i] - xc[3];
        o1.x = 2.f*acc[i][4] - xr[i] - xc[4];
        o1.y = 2.f*acc[i][5] - xr[i] - xc[5];
        o1.z = 2.f*acc[i][6] - xr[i] - xc[6];
        o1.w = 2.f*acc[i][7] - xr[i] - xc[7];
        *(float4*)&neg[rbase]     = o0;
        *(float4*)&neg[rbase + 4] = o1;
    }
}

// ------------------------------------------------------------------ top-20: warp per row, top-2 cached argmax tournament
__global__ __launch_bounds__(256) void topk_kernel(const float* __restrict__ neg, int* __restrict__ idxout) {
    int warp = threadIdx.x >> 5, lane = threadIdx.x & 31;
    int row = blockIdx.x * 8 + warp;
    const float* rp = neg + (long)row * NPT;

    unsigned key[32];
    #pragma unroll
    for (int j = 0; j < 32; j++) {
        unsigned u = __float_as_uint(rp[lane + 32 * j]);
        key[j] = (u & 0x80000000u) ? ~u : (u | 0x80000000u);  // order-preserving; real keys > 0
    }
    unsigned mask = 0u;   // removed entries
    unsigned bk = 0u, bk2 = 0u; int bj = 0, bj2 = 0;
    #pragma unroll
    for (int j = 0; j < 32; j++) {
        unsigned k = key[j];
        if (k > bk)       { bk2 = bk; bj2 = bj; bk = k; bj = j; }
        else if (k > bk2) { bk2 = k; bj2 = j; }
    }
    bool have2 = true;

    for (int sel = 0; sel < KNN; sel++) {
        unsigned wk = bk;
        unsigned wi = (unsigned)(lane + 32 * bj);
        #pragma unroll
        for (int off = 16; off; off >>= 1) {
            unsigned ok = __shfl_down_sync(0xffffffffu, wk, off);
            unsigned oi = __shfl_down_sync(0xffffffffu, wi, off);
            if (ok > wk || (ok == wk && oi < wi)) { wk = ok; wi = oi; }
        }
        wi = __shfl_sync(0xffffffffu, wi, 0);
        if (lane == 0) idxout[row * KNN + sel] = (int)wi;
        if ((wi & 31u) == (unsigned)lane) {
            mask |= 1u << (wi >> 5);
            if (have2) { bk = bk2; bj = bj2; have2 = false; }
            else {
                bk = 0u; bk2 = 0u; bj = 0; bj2 = 0;
                #pragma unroll
                for (int j = 0; j < 32; j++) {
                    unsigned k = ((mask >> j) & 1u) ? 0u : key[j];
                    if (k > bk)       { bk2 = bk; bj2 = bj; bk = k; bj = j; }
                    else if (k > bk2) { bk2 = k; bj2 = j; }
                }
                have2 = true;
            }
        }
    }
}

// ------------------------------------------------------------------ fused gather + edge conv + BN + leaky + max_k
// vectorized over 4 input channels (float4 smem reads)
template <int CIN, int CROW, int COUT, int P>
__global__ __launch_bounds__(128)
void conv_kernel(const float* __restrict__ X, const int* __restrict__ idx,
                 const float* __restrict__ w, const float* __restrict__ gam,
                 const float* __restrict__ bet, float* __restrict__ out) {
    constexpr int TPP = COUT / 4;
    constexpr int CP  = CROW + 4;
    extern __shared__ float sm[];
    float* wt = sm;                          // [CROW][COUT]  (w1^T, zero-padded c>=CIN)
    float* wd = wt + CROW * COUT;            // [CROW][COUT]  (w2-w1)^T
    float* nb = wd + CROW * COUT;            // [P][21][CP]
    int* sidx = (int*)(nb + P * 21 * CP);    // [P][KNN]

    int t = threadIdx.x;
    int b  = blockIdx.x / (NPT / P);
    int n0 = (blockIdx.x % (NPT / P)) * P;

    for (int i = t; i < CROW * COUT; i += 128) {
        int c = i / COUT, o = i % COUT;
        float w1 = (c < CIN) ? w[o * (2*CIN) + c] : 0.f;
        float w2 = (c < CIN) ? w[o * (2*CIN) + CIN + c] : 0.f;
        wt[c * COUT + o] = w1;
        wd[c * COUT + o] = w2 - w1;
    }
    for (int i = t; i < P * KNN; i += 128)
        sidx[i] = idx[((long)(b*NPT) + n0) * KNN + i];
    __syncthreads();

    constexpr int V4 = CROW / 4;
    for (int i = t; i < P * 21 * V4; i += 128) {
        int c4 = i % V4;
        int vec = i / V4;
        int p = vec / 21, k = vec % 21;
        int m = (k < KNN) ? sidx[p*KNN + k] : (n0 + p);
        float4 v = *(const float4*)&X[((long)(b*NPT) + m) * CROW + 4*c4];
        *(float4*)&nb[(p*21 + k) * CP + 4*c4] = v;
    }
    __syncthreads();

    int p  = t / TPP;
    int o4 = (t % TPP) * 4;
    float4 s[KNN];
    float4 u = make_float4(0.f, 0.f, 0.f, 0.f);
    #pragma unroll
    for (int k = 0; k < KNN; k++) s[k] = make_float4(0.f, 0.f, 0.f, 0.f);

    const float* nbp = nb + p * 21 * CP;
    #pragma unroll 1
    for (int c4i = 0; c4i < CROW/4; c4i++) {
        int c = 4 * c4i;
        float4 w1r[4], wdr[4];
        #pragma unroll
        for (int q = 0; q < 4; q++) {
            w1r[q] = *(const float4*)&wt[(c+q) * COUT + o4];
            wdr[q] = *(const float4*)&wd[(c+q) * COUT + o4];
        }
        float4 ct4 = *(const float4*)&nbp[20 * CP + c];
        float ctv[4] = {ct4.x, ct4.y, ct4.z, ct4.w};
        #pragma unroll
        for (int q = 0; q < 4; q++) {
            u.x += wdr[q].x * ctv[q]; u.y += wdr[q].y * ctv[q];
            u.z += wdr[q].z * ctv[q]; u.w += wdr[q].w * ctv[q];
        }
        #pragma unroll
        for (int k = 0; k < KNN; k++) {
            float4 nv = *(const float4*)&nbp[k * CP + c];
            float nvv[4] = {nv.x, nv.y, nv.z, nv.w};
            #pragma unroll
            for (int q = 0; q < 4; q++) {
                s[k].x += w1r[q].x * nvv[q]; s[k].y += w1r[q].y * nvv[q];
                s[k].z += w1r[q].z * nvv[q]; s[k].w += w1r[q].w * nvv[q];
            }
        }
    }
    float4 mx = s[0], mn = s[0];
    #pragma unroll
    for (int k = 1; k < KNN; k++) {
        mx.x = fmaxf(mx.x, s[k].x); mx.y = fmaxf(mx.y, s[k].y);
        mx.z = fmaxf(mx.z, s[k].z); mx.w = fmaxf(mx.w, s[k].w);
        mn.x = fminf(mn.x, s[k].x); mn.y = fminf(mn.y, s[k].y);
        mn.z = fminf(mn.z, s[k].z); mn.w = fminf(mn.w, s[k].w);
    }
    float inv = rsqrtf(1.0f + 1e-5f);
    float4 gmv = *(const float4*)&gam[o4];
    float4 btv = *(const float4*)&bet[o4];
    float4 res;
    { float a = gmv.x*inv; float base = ((a>=0.f)?mx.x:mn.x) + u.x; float v = a*base + btv.x; res.x = v>=0.f?v:0.2f*v; }
    { float a = gmv.y*inv; float base = ((a>=0.f)?mx.y:mn.y) + u.y; float v = a*base + btv.y; res.y = v>=0.f?v:0.2f*v; }
    { float a = gmv.z*inv; float base = ((a>=0.f)?mx.z:mn.z) + u.z; float v = a*base + btv.z; res.z = v>=0.f?v:0.2f*v; }
    { float a = gmv.w*inv; float base = ((a>=0.f)?mx.w:mn.w) + u.w; float v = a*base + btv.w; res.w = v>=0.f?v:0.2f*v; }
    int n = n0 + p;
    *(float4*)&out[((long)(b*NPT) + n) * COUT + o4] = res;
}

// ------------------------------------------------------------------ ew conv on concat(H3,S3) -> emb
__global__ __launch_bounds__(128)
void emb_kernel(const float* __restrict__ H3, const float* __restrict__ S3,
                const float* __restrict__ ew, const float* __restrict__ eg,
                const float* __restrict__ eb, float* __restrict__ emb) {
    extern __shared__ float sm[];
    float* wts  = sm;                 // [256][128]
    float* rows = wts + 256 * 128;    // [4][256]
    int t = threadIdx.x;
    for (int i = t; i < 256 * 128; i += 128) {
        int c = i / 128, o = i % 128;
        wts[c * 128 + o] = ew[o * 256 + c];
    }
    const int NITER = 8;
    int base = blockIdx.x * (4 * NITER);
    int pl = t / 32;
    int o4 = (t % 32) * 4;
    float inv = rsqrtf(1.0f + 1e-5f);
    for (int it = 0; it < NITER; it++) {
        __syncthreads();
        int p0 = base + it * 4;
        for (int i = t; i < 4 * 256; i += 128) {
            int pp = i / 256, c = i % 256;
            long pt = p0 + pp;
            rows[pp * 256 + c] = (c < 128) ? H3[pt * 128 + c] : S3[pt * 128 + c - 128];
        }
        __syncthreads();
        float4 acc = make_float4(0.f, 0.f, 0.f, 0.f);
        for (int c = 0; c < 256; c++) {
            float4 w4 = *(const float4*)&wts[c * 128 + o4];
            float xv = rows[pl * 256 + c];
            acc.x += w4.x * xv; acc.y += w4.y * xv;
            acc.z += w4.z * xv; acc.w += w4.w * xv;
        }
        float4 gmv = *(const float4*)&eg[o4];
        float4 btv = *(const float4*)&eb[o4];
        float4 r;
        { float v = gmv.x*inv*acc.x + btv.x; r.x = v>=0.f?v:0.2f*v; }
        { float v = gmv.y*inv*acc.y + btv.y; r.y = v>=0.f?v:0.2f*v; }
        { float v = gmv.z*inv*acc.z + btv.z; r.z = v>=0.f?v:0.2f*v; }
        { float v = gmv.w*inv*acc.w + btv.w; r.w = v>=0.f?v:0.2f*v; }
        long pt = p0 + pl;
        *(float4*)&emb[pt * 128 + o4] = r;
    }
}

// ------------------------------------------------------------------ attention pieces
__global__ void colsum_part(const float* __restrict__ emb, float* __restrict__ part) {
    int b = blockIdx.x, seg = blockIdx.y, f = threadIdx.x;
    const float* p = emb + ((long)(b*NPT) + seg*128) * 128 + f;
    float a = 0.f;
    #pragma unroll 4
    for (int n = 0; n < 128; n++) a += p[n * 128];
    part[(b*8 + seg) * 128 + f] = a;
}

__global__ void gc2_kernel(const float* __restrict__ part, const float* __restrict__ att_w,
                           float* __restrict__ gc) {
    __shared__ float es[128];
    int b = blockIdx.x, t = threadIdx.x;
    float a = 0.f;
    #pragma unroll
    for (int s = 0; s < 8; s++) a += part[(b*8 + s) * 128 + t];
    es[t] = a;
    __syncthreads();
    float gv = 0.f;
    for (int f = 0; f < 128; f++) gv += es[f] * att_w[f * 128 + t];
    gc[b * 128 + t] = tanhf(gv * (1.0f / NPT));
}

__global__ void sc_kernel(const float* __restrict__ emb, const float* __restrict__ gc,
                          float* __restrict__ att) {
    int warp = threadIdx.x >> 5, lane = threadIdx.x & 31;
    int pid = blockIdx.x * 4 + warp;
    int b = pid >> 10;
    float a = 0.f;
    #pragma unroll
    for (int j = 0; j < 4; j++) {
        int f = lane + 32 * j;
        a += emb[(long)pid * 128 + f] * gc[b * 128 + f];
    }
    #pragma unroll
    for (int off = 16; off; off >>= 1) a += __shfl_down_sync(0xffffffffu, a, off);
    if (lane == 0) att[pid] = 1.0f / (1.0f + expf(-a));
}

__global__ void pool_part(const float* __restrict__ emb, const float* __restrict__ att,
                          float* __restrict__ part) {
    int b = blockIdx.x, seg = blockIdx.y, f = threadIdx.x;
    const float* p = emb + ((long)(b*NPT) + seg*128) * 128 + f;
    const float* aw = att + b*NPT + seg*128;
    float a = 0.f;
    #pragma unroll 4
    for (int n = 0; n < 128; n++) a += p[n * 128] * aw[n];
    part[(b*8 + seg) * 128 + f] = a;
}

__global__ void pool_fin(const float* __restrict__ part, float* __restrict__ e) {
    int b = blockIdx.x, t = threadIdx.x;
    float a = 0.f;
    #pragma unroll
    for (int s = 0; s < 8; s++) a += part[(b*8 + s) * 128 + t];
    e[b * 128 + t] = a;
}

// ------------------------------------------------------------------ final scoring
__global__ void final_kernel(const float* __restrict__ e, const float* __restrict__ tn_w,
                             const float* __restrict__ tn_wb, const float* __restrict__ tn_bias,
                             const float* __restrict__ fc1_w, const float* __restrict__ fc1_b,
                             const float* __restrict__ sc_w, const float* __restrict__ sc_b,
                             float* __restrict__ out) {
    __shared__ float e1s[128], e2s[128], red[128], ts[16], hs[16];
    int b = blockIdx.x, tid = threadIdx.x;
    e1s[tid] = e[b * 128 + tid];
    e2s[tid] = e[(b + 8) * 128 + tid];
    __syncthreads();
    for (int tt = 0; tt < 16; tt++) {
        float inner = 0.f;
        const float* wrow = tn_w + (long)tid * 128 * 16 + tt;
        for (int gI = 0; gI < 128; gI++) inner += wrow[gI * 16] * e2s[gI];
        red[tid] = e1s[tid] * inner;
        __syncthreads();
        for (int s2 = 64; s2; s2 >>= 1) {
            if (tid < s2) red[tid] += red[tid + s2];
            __syncthreads();
        }
        if (tid == 0) ts[tt] = red[0];
        __syncthreads();
    }
    if (tid < 16) {
        float blk = 0.f;
        for (int c = 0; c < 128; c++) blk += tn_wb[tid * 256 + c] * e1s[c];
        for (int c = 0; c < 128; c++) blk += tn_wb[tid * 256 + 128 + c] * e2s[c];
        float v = ts[tid] + blk + tn_bias[tid];
        ts[tid] = v > 0.f ? v : 0.f;
    }
    __syncthreads();
    if (tid < 16) {
        float h = fc1_b[tid];
        for (int u2 = 0; u2 < 16; u2++) h += fc1_w[tid * 16 + u2] * ts[u2];
        hs[tid] = h > 0.f ? h : 0.f;
    }
    __syncthreads();
    if (tid == 0) {
        float z = sc_b[0];
        for (int u2 = 0; u2 < 16; u2++) z += sc_w[u2] * hs[u2];
        out[b] = 1.0f / (1.0f + expf(-z));
    }
}

// ------------------------------------------------------------------ host
template <typename T>
static float* symaddr(T& sym_) {
    void* p = nullptr;
    cudaGetSymbolAddress(&p, sym_);
    return (float*)p;
}

extern "C" void kernel_launch(void* const* d_in, const int* in_sizes, int n_in,
                              void* d_out, int out_size) {
    (void)in_sizes; (void)n_in; (void)out_size;
    const float* f1    = (const float*)d_in[0];
    const float* f2    = (const float*)d_in[1];
    const float* sw1   = (const float*)d_in[2];
    const float* sg1   = (const float*)d_in[3];
    const float* sb1   = (const float*)d_in[4];
    const float* fw1   = (const float*)d_in[5];
    const float* fg1   = (const float*)d_in[6];
    const float* fb1   = (const float*)d_in[7];
    const float* sw2   = (const float*)d_in[8];
    const float* sg2   = (const float*)d_in[9];
    const float* sb2   = (const float*)d_in[10];
    const float* fw2   = (const float*)d_in[11];
    const float* fg2   = (const float*)d_in[12];
    const float* fb2   = (const float*)d_in[13];
    const float* sw3   = (const float*)d_in[14];
    const float* sg3   = (const float*)d_in[15];
    const float* sb3   = (const float*)d_in[16];
    const float* fw3   = (const float*)d_in[17];
    const float* fg3   = (const float*)d_in[18];
    const float* fb3   = (const float*)d_in[19];
    const float* ew    = (const float*)d_in[20];
    const float* eg    = (const float*)d_in[21];
    const float* ebv   = (const float*)d_in[22];
    const float* att_w = (const float*)d_in[23];
    const float* tn_w  = (const float*)d_in[24];
    const float* tn_wb = (const float*)d_in[25];
    const float* tn_b  = (const float*)d_in[26];
    const float* fc1_w = (const float*)d_in[27];
    const float* fc1_b = (const float*)d_in[28];
    const float* sc_w  = (const float*)d_in[29];
    const float* sc_b  = (const float*)d_in[30];
    float* out = (float*)d_out;

    float* negp  = symaddr(g_neg);
    int*   idxp  = (int*)symaddr(g_idx);
    float* xxp   = symaddr(g_xx);
    float* x0p   = symaddr(g_x0);
    float* s0p   = symaddr(g_s0);
    float* h1p   = symaddr(g_h1);
    float* h2p   = symaddr(g_h2);
    float* h3p   = symaddr(g_h3);
    float* embp  = symaddr(g_emb);
    float* partp = symaddr(g_part);
    float* gcp   = symaddr(g_gc);
    float* ep    = symaddr(g_e);

    const int SM_C1 = (2*4*64    + 8*21*8  ) * 4 + 8*KNN*4;   // conv<3,4,64,8>
    const int SM_C2 = (2*64*64   + 8*21*68 ) * 4 + 8*KNN*4;   // conv<64,64,64,8>
    const int SM_C3 = (2*64*128  + 4*21*68 ) * 4 + 4*KNN*4;   // conv<64,64,128,4>
    const int SM_C4 = (2*128*64  + 8*21*132) * 4 + 8*KNN*4;   // conv<128,128,64,8>
    const int SM_EW = (256*128 + 4*256) * 4;

    cudaFuncSetAttribute(conv_kernel<64,64,64,8>,   cudaFuncAttributeMaxDynamicSharedMemorySize, SM_C2);
    cudaFuncSetAttribute(conv_kernel<64,64,128,4>,  cudaFuncAttributeMaxDynamicSharedMemorySize, SM_C3);
    cudaFuncSetAttribute(conv_kernel<128,128,64,8>, cudaFuncAttributeMaxDynamicSharedMemorySize, SM_C4);
    cudaFuncSetAttribute(emb_kernel,                cudaFuncAttributeMaxDynamicSharedMemorySize, SM_EW);

    transpose_kernel<<<(NB*131*NPT + 255) / 256, 256>>>(f1, f2, x0p, s0p);

    // ---- xyz chain: 3 -> 64 -> 64 -> 128 (both graphs batched, h buffers reused) ----
    xx_kernel<4><<<NROW/256, 256>>>(x0p, xxp);
    dist_kernel<4><<<dim3(8,8,NB), 256>>>(x0p, xxp, negp);
    topk_kernel<<<NROW/8, 256>>>(negp, idxp);
    conv_kernel<3,4,64,8><<<NB*NPT/8, 128, SM_C1>>>(x0p, idxp, sw1, sg1, sb1, h1p);

    xx_kernel<64><<<NROW/256, 256>>>(h1p, xxp);
    dist_kernel<64><<<dim3(8,8,NB), 256>>>(h1p, xxp, negp);
    topk_kernel<<<NROW/8, 256>>>(negp, idxp);
    conv_kernel<64,64,64,8><<<NB*NPT/8, 128, SM_C2>>>(h1p, idxp, sw2, sg2, sb2, h2p);

    xx_kernel<64><<<NROW/256, 256>>>(h2p, xxp);
    dist_kernel<64><<<dim3(8,8,NB), 256>>>(h2p, xxp, negp);
    topk_kernel<<<NROW/8, 256>>>(negp, idxp);
    conv_kernel<64,64,128,4><<<NB*NPT/4, 128, SM_C3>>>(h2p, idxp, sw3, sg3, sb3, h3p);

    // ---- sem chain: 128 -> 64 -> 64 -> 128 (reuses h1p/h2p as temps, writes emb input via h buffers) ----
    xx_kernel<128><<<NROW/256, 256>>>(s0p, xxp);
    dist_kernel<128><<<dim3(8,8,NB), 256>>>(s0p, xxp, negp);
    topk_kernel<<<NROW/8, 256>>>(negp, idxp);
    conv_kernel<128,128,64,8><<<NB*NPT/8, 128, SM_C4>>>(s0p, idxp, fw1, fg1, fb1, h1p);

    xx_kernel<64><<<NROW/256, 256>>>(h1p, xxp);
    dist_kernel<64><<<dim3(8,8,NB), 256>>>(h1p, xxp, negp);
    topk_kernel<<<NROW/8, 256>>>(negp, idxp);
    conv_kernel<64,64,64,8><<<NB*NPT/8, 128, SM_C2>>>(h1p, idxp, fw2, fg2, fb2, h2p);

    xx_kernel<64><<<NROW/256, 256>>>(h2p, xxp);
    dist_kernel<64><<<dim3(8,8,NB), 256>>>(h2p, xxp, negp);
    topk_kernel<<<NROW/8, 256>>>(negp, idxp);
    conv_kernel<64,64,128,4><<<NB*NPT/4, 128, SM_C3>>>(h2p, idxp, fw3, fg3, fb3, s0p);  // s0p reused as S3

    // ---- fuse + attention (all 16 batches) ----
    emb_kernel<<<NROW/32, 128, SM_EW>>>(h3p, s0p, ew, eg, ebv, embp);

    float* att_out = out + 8;                       // att1 (b 0..7) then att2 (b 8..15), contiguous
    colsum_part<<<dim3(NB, 8), 128>>>(embp, partp);
    gc2_kernel<<<NB, 128>>>(partp, att_w, gcp);
    sc_kernel<<<NROW/4, 128>>>(embp, gcp, att_out);
    pool_part<<<dim3(NB, 8), 128>>>(embp, att_out, partp);
    pool_fin<<<NB, 128>>>(partp, ep);

    final_kernel<<<BB, 128>>>(ep, tn_w, tn_wb, tn_b, fc1_w, fc1_b, sc_w, sc_b, out);
}

// round 6
// speedup vs baseline: 2.2190x; 1.1534x over previous
#include <cuda_runtime.h>
#include <math.h>
#include <stdint.h>

#define BB   8
#define NB   16          // both graphs merged into one batch
#define NPT  1024
#define KNN  20
#define NROW (NB*NPT)    // 16384

// ------------------------------------------------------------------ packed fp32x2 helpers
__device__ __forceinline__ void ffma2(unsigned long long& d, unsigned long long a, unsigned long long b) {
    asm("fma.rn.f32x2 %0, %1, %2, %0;" : "+l"(d) : "l"(a), "l"(b));
}
__device__ __forceinline__ unsigned long long dup2(float x) {
    unsigned long long r;
    asm("mov.b64 %0, {%1, %1};" : "=l"(r) : "f"(x));
    return r;
}
__device__ __forceinline__ float2 unpk2(unsigned long long v) {
    float2 r;
    asm("mov.b64 {%0, %1}, %2;" : "=f"(r.x), "=f"(r.y) : "l"(v));
    return r;
}

// ------------------------------------------------------------------ scratch
__device__ float g_neg[NROW*NPT];      // 64 MB distance matrix (reused)
__device__ int   g_idx[NROW*KNN];
__device__ float g_xx [NROW];
__device__ float g_x0 [NROW*4];
__device__ float g_s0 [NROW*128];
__device__ float g_h1 [NROW*64];
__device__ float g_h2 [NROW*64];
__device__ float g_h3 [NROW*128];
__device__ float g_emb[NROW*128];
__device__ float g_part[NB*8*128];
__device__ float g_gc  [NB*128];
__device__ float g_e   [NB*128];

// ------------------------------------------------------------------ transpose both inputs (B,C,N) -> point-major
__global__ void transpose_kernel(const float* __restrict__ f1, const float* __restrict__ f2,
                                 float* __restrict__ x0, float* __restrict__ s0) {
    int j = blockIdx.x * blockDim.x + threadIdx.x;
    int total = NB * 131 * NPT;
    if (j >= total) return;
    int n = j % NPT;
    int c = (j / NPT) % 131;
    int b = j / (131 * NPT);
    const float* in = (b < BB) ? f1 : f2;
    float v = in[((long)(b & 7) * 131 + c) * NPT + n];
    if (c < 3) {
        x0[(b*NPT + n)*4 + c] = v;
        if (c == 0) x0[(b*NPT + n)*4 + 3] = 0.0f;
    } else {
        s0[((long)(b*NPT) + n)*128 + (c - 3)] = v;
    }
}

// ------------------------------------------------------------------ per-point squared norm
template <int CROW>
__global__ void xx_kernel(const float* __restrict__ X, float* __restrict__ xx) {
    int j = blockIdx.x * 256 + threadIdx.x;
    if (j >= NROW) return;
    const float* r = X + (long)j * CROW;
    float a = 0.f;
    #pragma unroll
    for (int c = 0; c < CROW; c++) a += r[c] * r[c];
    xx[j] = a;
}

// ------------------------------------------------------------------ neg distance: 2*X.X^T - xx_n - xx_m
// 128x128 tile, 256 threads, 8x8 register micro-tile, packed f32x2 FMA
template <int CROW>
__global__ __launch_bounds__(256) void dist_kernel(const float* __restrict__ X,
                                                   const float* __restrict__ xx,
                                                   float* __restrict__ neg) {
    constexpr int TC = (CROW < 16) ? CROW : 16;
    constexpr int LDW = 132;
    __shared__ float As[TC][LDW];
    __shared__ float Bs[TC][LDW];
    int b = blockIdx.z;
    int row0 = blockIdx.y * 128;
    int col0 = blockIdx.x * 128;
    int t = threadIdx.x;
    int tx = t & 15, ty = t >> 4;
    unsigned long long acc2[8][4];
    #pragma unroll
    for (int i = 0; i < 8; i++)
        #pragma unroll
        for (int j = 0; j < 4; j++) acc2[i][j] = 0ull;

    for (int c0 = 0; c0 < CROW; c0 += TC) {
        constexpr int NLD = (128 * TC) / 256;
        #pragma unroll
        for (int l = 0; l < NLD; l++) {
            int i = t + l * 256;
            int r = i / TC, c = i % TC;
            As[c][r] = X[((long)(b*NPT) + row0 + r) * CROW + c0 + c];
            Bs[c][r] = X[((long)(b*NPT) + col0 + r) * CROW + c0 + c];
        }
        __syncthreads();
        #pragma unroll
        for (int c = 0; c < TC; c++) {
            float4 a0 = *(const float4*)&As[c][ty*8];
            float4 a1 = *(const float4*)&As[c][ty*8+4];
            ulonglong2 b01 = *(const ulonglong2*)&Bs[c][tx*8];
            ulonglong2 b23 = *(const ulonglong2*)&Bs[c][tx*8+4];
            unsigned long long bp[4] = {b01.x, b01.y, b23.x, b23.y};
            unsigned long long ap[8];
            ap[0]=dup2(a0.x); ap[1]=dup2(a0.y); ap[2]=dup2(a0.z); ap[3]=dup2(a0.w);
            ap[4]=dup2(a1.x); ap[5]=dup2(a1.y); ap[6]=dup2(a1.z); ap[7]=dup2(a1.w);
            #pragma unroll
            for (int i = 0; i < 8; i++)
                #pragma unroll
                for (int j = 0; j < 4; j++) ffma2(acc2[i][j], ap[i], bp[j]);
        }
        __syncthreads();
    }
    float xr[8], xc[8];
    #pragma unroll
    for (int i = 0; i < 8; i++) {
        xr[i] = xx[b*NPT + row0 + ty*8 + i];
        xc[i] = xx[b*NPT + col0 + tx*8 + i];
    }
    #pragma unroll
    for (int i = 0; i < 8; i++) {
        long rbase = ((long)(b*NPT) + row0 + ty*8 + i) * NPT + col0 + tx*8;
        float2 p0 = unpk2(acc2[i][0]);
        float2 p1 = unpk2(acc2[i][1]);
        float2 p2 = unpk2(acc2[i][2]);
        float2 p3 = unpk2(acc2[i][3]);
        float4 o0, o1;
        o0.x = 2.f*p0.x - xr[i] - xc[0];
        o0.y = 2.f*p0.y - xr[i] - xc[1];
        o0.z = 2.f*p1.x - xr[i] - xc[2];
        o0.w = 2.f*p1.y - xr[i] - xc[3];
        o1.x = 2.f*p2.x - xr[i] - xc[4];
        o1.y = 2.f*p2.y - xr[i] - xc[5];
        o1.z = 2.f*p3.x - xr[i] - xc[6];
        o1.w = 2.f*p3.y - xr[i] - xc[7];
        *(float4*)&neg[rbase]     = o0;
        *(float4*)&neg[rbase + 4] = o1;
    }
}

// ------------------------------------------------------------------ top-20: warp per row, REDUX argmax + per-lane top-4 cache
// Keys mapped order-preserving to u32 (> 0 always); 0 = empty sentinel.
__global__ __launch_bounds__(256) void topk_kernel(const float* __restrict__ neg, int* __restrict__ idxout) {
    int warp = threadIdx.x >> 5, lane = threadIdx.x & 31;
    int row = blockIdx.x * 8 + warp;
    const float* rp = neg + (long)row * NPT;

    unsigned ck0=0,ck1=0,ck2=0,ck3=0;
    unsigned ci0=0,ci1=0,ci2=0,ci3=0;
    #pragma unroll
    for (int j = 0; j < 32; j++) {
        unsigned u = __float_as_uint(rp[lane + 32*j]);
        unsigned k = (u & 0x80000000u) ? ~u : (u | 0x80000000u);
        unsigned gi = (unsigned)(lane + 32*j);
        if (k > ck3) {
            if (k > ck0)      { ck3=ck2;ci3=ci2; ck2=ck1;ci2=ci1; ck1=ck0;ci1=ci0; ck0=k;ci0=gi; }
            else if (k > ck1) { ck3=ck2;ci3=ci2; ck2=ck1;ci2=ci1; ck1=k;ci1=gi; }
            else if (k > ck2) { ck3=ck2;ci3=ci2; ck2=k;ci2=gi; }
            else              { ck3=k;ci3=gi; }
        }
    }
    unsigned removed = 0u;
    int navail = 4;
    for (int sel = 0; sel < KNN; sel++) {
        unsigned maxk = __reduce_max_sync(0xffffffffu, ck0);
        unsigned cand = (ck0 == maxk) ? ci0 : 0xffffffffu;
        unsigned widx = __reduce_min_sync(0xffffffffu, cand);
        if (lane == 0) idxout[row*KNN + sel] = (int)widx;
        if (ck0 == maxk && ci0 == widx) {        // unique owner
            removed |= 1u << (widx >> 5);
            ck0=ck1;ci0=ci1; ck1=ck2;ci1=ci2; ck2=ck3;ci2=ci3; ck3=0;ci3=0;
            if (--navail == 0) {                  // rare refill (lane needed 5+ wins)
                ck0=ck1=ck2=ck3=0; ci0=ci1=ci2=ci3=0;
                for (int j = 0; j < 32; j++) {
                    if ((removed >> j) & 1u) continue;
                    unsigned u = __float_as_uint(rp[lane + 32*j]);
                    unsigned k = (u & 0x80000000u) ? ~u : (u | 0x80000000u);
                    unsigned gi = (unsigned)(lane + 32*j);
                    if (k > ck3) {
                        if (k > ck0)      { ck3=ck2;ci3=ci2; ck2=ck1;ci2=ci1; ck1=ck0;ci1=ci0; ck0=k;ci0=gi; }
                        else if (k > ck1) { ck3=ck2;ci3=ci2; ck2=ck1;ci2=ci1; ck1=k;ci1=gi; }
                        else if (k > ck2) { ck3=ck2;ci3=ci2; ck2=k;ci2=gi; }
                        else              { ck3=k;ci3=gi; }
                    }
                }
                navail = 4;
            }
        }
    }
}

// ------------------------------------------------------------------ fused gather + edge conv + BN + leaky + max_k
// packed f32x2 FMA over output-channel pairs
template <int CIN, int CROW, int COUT, int P>
__global__ __launch_bounds__(128)
void conv_kernel(const float* __restrict__ X, const int* __restrict__ idx,
                 const float* __restrict__ w, const float* __restrict__ gam,
                 const float* __restrict__ bet, float* __restrict__ out) {
    constexpr int TPP = COUT / 4;
    constexpr int CP  = CROW + 4;
    extern __shared__ float sm[];
    float* wt = sm;                          // [CROW][COUT]  (w1^T, zero-padded c>=CIN)
    float* wd = wt + CROW * COUT;            // [CROW][COUT]  (w2-w1)^T
    float* nb = wd + CROW * COUT;            // [P][21][CP]
    int* sidx = (int*)(nb + P * 21 * CP);    // [P][KNN]

    int t = threadIdx.x;
    int b  = blockIdx.x / (NPT / P);
    int n0 = (blockIdx.x % (NPT / P)) * P;

    for (int i = t; i < CROW * COUT; i += 128) {
        int c = i / COUT, o = i % COUT;
        float w1 = (c < CIN) ? w[o * (2*CIN) + c] : 0.f;
        float w2 = (c < CIN) ? w[o * (2*CIN) + CIN + c] : 0.f;
        wt[c * COUT + o] = w1;
        wd[c * COUT + o] = w2 - w1;
    }
    for (int i = t; i < P * KNN; i += 128)
        sidx[i] = idx[((long)(b*NPT) + n0) * KNN + i];
    __syncthreads();

    constexpr int V4 = CROW / 4;
    for (int i = t; i < P * 21 * V4; i += 128) {
        int c4 = i % V4;
        int vec = i / V4;
        int p = vec / 21, k = vec % 21;
        int m = (k < KNN) ? sidx[p*KNN + k] : (n0 + p);
        float4 v = *(const float4*)&X[((long)(b*NPT) + m) * CROW + 4*c4];
        *(float4*)&nb[(p*21 + k) * CP + 4*c4] = v;
    }
    __syncthreads();

    int p  = t / TPP;
    int o4 = (t % TPP) * 4;
    unsigned long long s2[KNN][2];
    unsigned long long u2[2] = {0ull, 0ull};
    #pragma unroll
    for (int k = 0; k < KNN; k++) { s2[k][0] = 0ull; s2[k][1] = 0ull; }

    const float* nbp = nb + p * 21 * CP;
    #pragma unroll 1
    for (int c4i = 0; c4i < CROW/4; c4i++) {
        int c = 4 * c4i;
        ulonglong2 w1p[4], wdp[4];
        #pragma unroll
        for (int q = 0; q < 4; q++) {
            w1p[q] = *(const ulonglong2*)&wt[(c+q) * COUT + o4];
            wdp[q] = *(const ulonglong2*)&wd[(c+q) * COUT + o4];
        }
        float4 ct4 = *(const float4*)&nbp[20 * CP + c];
        unsigned long long ctd[4] = {dup2(ct4.x), dup2(ct4.y), dup2(ct4.z), dup2(ct4.w)};
        #pragma unroll
        for (int q = 0; q < 4; q++) {
            ffma2(u2[0], wdp[q].x, ctd[q]);
            ffma2(u2[1], wdp[q].y, ctd[q]);
        }
        #pragma unroll
        for (int k = 0; k < KNN; k++) {
            float4 nv = *(const float4*)&nbp[k * CP + c];
            unsigned long long n0d = dup2(nv.x), n1d = dup2(nv.y), n2d = dup2(nv.z), n3d = dup2(nv.w);
            ffma2(s2[k][0], w1p[0].x, n0d); ffma2(s2[k][1], w1p[0].y, n0d);
            ffma2(s2[k][0], w1p[1].x, n1d); ffma2(s2[k][1], w1p[1].y, n1d);
            ffma2(s2[k][0], w1p[2].x, n2d); ffma2(s2[k][1], w1p[2].y, n2d);
            ffma2(s2[k][0], w1p[3].x, n3d); ffma2(s2[k][1], w1p[3].y, n3d);
        }
    }
    float2 sxy = unpk2(s2[0][0]);
    float2 szw = unpk2(s2[0][1]);
    float4 mx = make_float4(sxy.x, sxy.y, szw.x, szw.y);
    float4 mn = mx;
    #pragma unroll
    for (int k = 1; k < KNN; k++) {
        float2 a = unpk2(s2[k][0]);
        float2 bq = unpk2(s2[k][1]);
        mx.x = fmaxf(mx.x, a.x);  mx.y = fmaxf(mx.y, a.y);
        mx.z = fmaxf(mx.z, bq.x); mx.w = fmaxf(mx.w, bq.y);
        mn.x = fminf(mn.x, a.x);  mn.y = fminf(mn.y, a.y);
        mn.z = fminf(mn.z, bq.x); mn.w = fminf(mn.w, bq.y);
    }
    float2 uxy = unpk2(u2[0]);
    float2 uzw = unpk2(u2[1]);
    float inv = rsqrtf(1.0f + 1e-5f);
    float4 gmv = *(const float4*)&gam[o4];
    float4 btv = *(const float4*)&bet[o4];
    float4 res;
    { float a = gmv.x*inv; float base = ((a>=0.f)?mx.x:mn.x) + uxy.x; float v = a*base + btv.x; res.x = v>=0.f?v:0.2f*v; }
    { float a = gmv.y*inv; float base = ((a>=0.f)?mx.y:mn.y) + uxy.y; float v = a*base + btv.y; res.y = v>=0.f?v:0.2f*v; }
    { float a = gmv.z*inv; float base = ((a>=0.f)?mx.z:mn.z) + uzw.x; float v = a*base + btv.z; res.z = v>=0.f?v:0.2f*v; }
    { float a = gmv.w*inv; float base = ((a>=0.f)?mx.w:mn.w) + uzw.y; float v = a*base + btv.w; res.w = v>=0.f?v:0.2f*v; }
    int n = n0 + p;
    *(float4*)&out[((long)(b*NPT) + n) * COUT + o4] = res;
}

// ------------------------------------------------------------------ ew conv on concat(H3,S3) -> emb (packed FMA)
__global__ __launch_bounds__(128)
void emb_kernel(const float* __restrict__ H3, const float* __restrict__ S3,
                const float* __restrict__ ew, const float* __restrict__ eg,
                const float* __restrict__ eb, float* __restrict__ emb) {
    extern __shared__ float sm[];
    float* wts  = sm;                 // [256][128]
    float* rows = wts + 256 * 128;    // [4][256]
    int t = threadIdx.x;
    for (int i = t; i < 256 * 128; i += 128) {
        int c = i / 128, o = i % 128;
        wts[c * 128 + o] = ew[o * 256 + c];
    }
    const int NITER = 8;
    int base = blockIdx.x * (4 * NITER);
    int pl = t / 32;
    int o4 = (t % 32) * 4;
    float inv = rsqrtf(1.0f + 1e-5f);
    for (int it = 0; it < NITER; it++) {
        __syncthreads();
        int p0 = base + it * 4;
        for (int i = t; i < 4 * 256; i += 128) {
            int pp = i / 256, c = i % 256;
            long pt = p0 + pp;
            rows[pp * 256 + c] = (c < 128) ? H3[pt * 128 + c] : S3[pt * 128 + c - 128];
        }
        __syncthreads();
        unsigned long long acc2[2] = {0ull, 0ull};
        for (int c = 0; c < 256; c++) {
            ulonglong2 wp = *(const ulonglong2*)&wts[c * 128 + o4];
            unsigned long long xd = dup2(rows[pl * 256 + c]);
            ffma2(acc2[0], wp.x, xd);
            ffma2(acc2[1], wp.y, xd);
        }
        float2 axy = unpk2(acc2[0]);
        float2 azw = unpk2(acc2[1]);
        float4 gmv = *(const float4*)&eg[o4];
        float4 btv = *(const float4*)&eb[o4];
        float4 r;
        { float v = gmv.x*inv*axy.x + btv.x; r.x = v>=0.f?v:0.2f*v; }
        { float v = gmv.y*inv*axy.y + btv.y; r.y = v>=0.f?v:0.2f*v; }
        { float v = gmv.z*inv*azw.x + btv.z; r.z = v>=0.f?v:0.2f*v; }
        { float v = gmv.w*inv*azw.y + btv.w; r.w = v>=0.f?v:0.2f*v; }
        long pt = p0 + pl;
        *(float4*)&emb[pt * 128 + o4] = r;
    }
}

// ------------------------------------------------------------------ attention pieces
__global__ void colsum_part(const float* __restrict__ emb, float* __restrict__ part) {
    int b = blockIdx.x, seg = blockIdx.y, f = threadIdx.x;
    const float* p = emb + ((long)(b*NPT) + seg*128) * 128 + f;
    float a = 0.f;
    #pragma unroll 4
    for (int n = 0; n < 128; n++) a += p[n * 128];
    part[(b*8 + seg) * 128 + f] = a;
}

__global__ void gc2_kernel(const float* __restrict__ part, const float* __restrict__ att_w,
                           float* __restrict__ gc) {
    __shared__ float es[128];
    int b = blockIdx.x, t = threadIdx.x;
    float a = 0.f;
    #pragma unroll
    for (int s = 0; s < 8; s++) a += part[(b*8 + s) * 128 + t];
    es[t] = a;
    __syncthreads();
    float gv = 0.f;
    for (int f = 0; f < 128; f++) gv += es[f] * att_w[f * 128 + t];
    gc[b * 128 + t] = tanhf(gv * (1.0f / NPT));
}

__global__ void sc_kernel(const float* __restrict__ emb, const float* __restrict__ gc,
                          float* __restrict__ att) {
    int warp = threadIdx.x >> 5, lane = threadIdx.x & 31;
    int pid = blockIdx.x * 4 + warp;
    int b = pid >> 10;
    float a = 0.f;
    #pragma unroll
    for (int j = 0; j < 4; j++) {
        int f = lane + 32 * j;
        a += emb[(long)pid * 128 + f] * gc[b * 128 + f];
    }
    #pragma unroll
    for (int off = 16; off; off >>= 1) a += __shfl_down_sync(0xffffffffu, a, off);
    if (lane == 0) att[pid] = 1.0f / (1.0f + expf(-a));
}

__global__ void pool_part(const float* __restrict__ emb, const float* __restrict__ att,
                          float* __restrict__ part) {
    int b = blockIdx.x, seg = blockIdx.y, f = threadIdx.x;
    const float* p = emb + ((long)(b*NPT) + seg*128) * 128 + f;
    const float* aw = att + b*NPT + seg*128;
    float a = 0.f;
    #pragma unroll 4
    for (int n = 0; n < 128; n++) a += p[n * 128] * aw[n];
    part[(b*8 + seg) * 128 + f] = a;
}

__global__ void pool_fin(const float* __restrict__ part, float* __restrict__ e) {
    int b = blockIdx.x, t = threadIdx.x;
    float a = 0.f;
    #pragma unroll
    for (int s = 0; s < 8; s++) a += part[(b*8 + s) * 128 + t];
    e[b * 128 + t] = a;
}

// ------------------------------------------------------------------ final scoring
__global__ void final_kernel(const float* __restrict__ e, const float* __restrict__ tn_w,
                             const float* __restrict__ tn_wb, const float* __restrict__ tn_bias,
                             const float* __restrict__ fc1_w, const float* __restrict__ fc1_b,
                             const float* __restrict__ sc_w, const float* __restrict__ sc_b,
                             float* __restrict__ out) {
    __shared__ float e1s[128], e2s[128], red[128], ts[16], hs[16];
    int b = blockIdx.x, tid = threadIdx.x;
    e1s[tid] = e[b * 128 + tid];
    e2s[tid] = e[(b + 8) * 128 + tid];
    __syncthreads();
    for (int tt = 0; tt < 16; tt++) {
        float inner = 0.f;
        const float* wrow = tn_w + (long)tid * 128 * 16 + tt;
        for (int gI = 0; gI < 128; gI++) inner += wrow[gI * 16] * e2s[gI];
        red[tid] = e1s[tid] * inner;
        __syncthreads();
        for (int s2 = 64; s2; s2 >>= 1) {
            if (tid < s2) red[tid] += red[tid + s2];
            __syncthreads();
        }
        if (tid == 0) ts[tt] = red[0];
        __syncthreads();
    }
    if (tid < 16) {
        float blk = 0.f;
        for (int c = 0; c < 128; c++) blk += tn_wb[tid * 256 + c] * e1s[c];
        for (int c = 0; c < 128; c++) blk += tn_wb[tid * 256 + 128 + c] * e2s[c];
        float v = ts[tid] + blk + tn_bias[tid];
        ts[tid] = v > 0.f ? v : 0.f;
    }
    __syncthreads();
    if (tid < 16) {
        float h = fc1_b[tid];
        for (int u2 = 0; u2 < 16; u2++) h += fc1_w[tid * 16 + u2] * ts[u2];
        hs[tid] = h > 0.f ? h : 0.f;
    }
    __syncthreads();
    if (tid == 0) {
        float z = sc_b[0];
        for (int u2 = 0; u2 < 16; u2++) z += sc_w[u2] * hs[u2];
        out[b] = 1.0f / (1.0f + expf(-z));
    }
}

// ------------------------------------------------------------------ host
template <typename T>
static float* symaddr(T& sym_) {
    void* p = nullptr;
    cudaGetSymbolAddress(&p, sym_);
    return (float*)p;
}

extern "C" void kernel_launch(void* const* d_in, const int* in_sizes, int n_in,
                              void* d_out, int out_size) {
    (void)in_sizes; (void)n_in; (void)out_size;
    const float* f1    = (const float*)d_in[0];
    const float* f2    = (const float*)d_in[1];
    const float* sw1   = (const float*)d_in[2];
    const float* sg1   = (const float*)d_in[3];
    const float* sb1   = (const float*)d_in[4];
    const float* fw1   = (const float*)d_in[5];
    const float* fg1   = (const float*)d_in[6];
    const float* fb1   = (const float*)d_in[7];
    const float* sw2   = (const float*)d_in[8];
    const float* sg2   = (const float*)d_in[9];
    const float* sb2   = (const float*)d_in[10];
    const float* fw2   = (const float*)d_in[11];
    const float* fg2   = (const float*)d_in[12];
    const float* fb2   = (const float*)d_in[13];
    const float* sw3   = (const float*)d_in[14];
    const float* sg3   = (const float*)d_in[15];
    const float* sb3   = (const float*)d_in[16];
    const float* fw3   = (const float*)d_in[17];
    const float* fg3   = (const float*)d_in[18];
    const float* fb3   = (const float*)d_in[19];
    const float* ew    = (const float*)d_in[20];
    const float* eg    = (const float*)d_in[21];
    const float* ebv   = (const float*)d_in[22];
    const float* att_w = (const float*)d_in[23];
    const float* tn_w  = (const float*)d_in[24];
    const float* tn_wb = (const float*)d_in[25];
    const float* tn_b  = (const float*)d_in[26];
    const float* fc1_w = (const float*)d_in[27];
    const float* fc1_b = (const float*)d_in[28];
    const float* sc_w  = (const float*)d_in[29];
    const float* sc_b  = (const float*)d_in[30];
    float* out = (float*)d_out;

    float* negp  = symaddr(g_neg);
    int*   idxp  = (int*)symaddr(g_idx);
    float* xxp   = symaddr(g_xx);
    float* x0p   = symaddr(g_x0);
    float* s0p   = symaddr(g_s0);
    float* h1p   = symaddr(g_h1);
    float* h2p   = symaddr(g_h2);
    float* h3p   = symaddr(g_h3);
    float* embp  = symaddr(g_emb);
    float* partp = symaddr(g_part);
    float* gcp   = symaddr(g_gc);
    float* ep    = symaddr(g_e);

    const int SM_C1 = (2*4*64    + 8*21*8  ) * 4 + 8*KNN*4;   // conv<3,4,64,8>
    const int SM_C2 = (2*64*64   + 8*21*68 ) * 4 + 8*KNN*4;   // conv<64,64,64,8>
    const int SM_C3 = (2*64*128  + 4*21*68 ) * 4 + 4*KNN*4;   // conv<64,64,128,4>
    const int SM_C4 = (2*128*64  + 8*21*132) * 4 + 8*KNN*4;   // conv<128,128,64,8>
    const int SM_EW = (256*128 + 4*256) * 4;

    cudaFuncSetAttribute(conv_kernel<64,64,64,8>,   cudaFuncAttributeMaxDynamicSharedMemorySize, SM_C2);
    cudaFuncSetAttribute(conv_kernel<64,64,128,4>,  cudaFuncAttributeMaxDynamicSharedMemorySize, SM_C3);
    cudaFuncSetAttribute(conv_kernel<128,128,64,8>, cudaFuncAttributeMaxDynamicSharedMemorySize, SM_C4);
    cudaFuncSetAttribute(emb_kernel,                cudaFuncAttributeMaxDynamicSharedMemorySize, SM_EW);

    transpose_kernel<<<(NB*131*NPT + 255) / 256, 256>>>(f1, f2, x0p, s0p);

    // ---- xyz chain: 3 -> 64 -> 64 -> 128 ----
    xx_kernel<4><<<NROW/256, 256>>>(x0p, xxp);
    dist_kernel<4><<<dim3(8,8,NB), 256>>>(x0p, xxp, negp);
    topk_kernel<<<NROW/8, 256>>>(negp, idxp);
    conv_kernel<3,4,64,8><<<NB*NPT/8, 128, SM_C1>>>(x0p, idxp, sw1, sg1, sb1, h1p);

    xx_kernel<64><<<NROW/256, 256>>>(h1p, xxp);
    dist_kernel<64><<<dim3(8,8,NB), 256>>>(h1p, xxp, negp);
    topk_kernel<<<NROW/8, 256>>>(negp, idxp);
    conv_kernel<64,64,64,8><<<NB*NPT/8, 128, SM_C2>>>(h1p, idxp, sw2, sg2, sb2, h2p);

    xx_kernel<64><<<NROW/256, 256>>>(h2p, xxp);
    dist_kernel<64><<<dim3(8,8,NB), 256>>>(h2p, xxp, negp);
    topk_kernel<<<NROW/8, 256>>>(negp, idxp);
    conv_kernel<64,64,128,4><<<NB*NPT/4, 128, SM_C3>>>(h2p, idxp, sw3, sg3, sb3, h3p);

    // ---- sem chain: 128 -> 64 -> 64 -> 128 ----
    xx_kernel<128><<<NROW/256, 256>>>(s0p, xxp);
    dist_kernel<128><<<dim3(8,8,NB), 256>>>(s0p, xxp, negp);
    topk_kernel<<<NROW/8, 256>>>(negp, idxp);
    conv_kernel<128,128,64,8><<<NB*NPT/8, 128, SM_C4>>>(s0p, idxp, fw1, fg1, fb1, h1p);

    xx_kernel<64><<<NROW/256, 256>>>(h1p, xxp);
    dist_kernel<64><<<dim3(8,8,NB), 256>>>(h1p, xxp, negp);
    topk_kernel<<<NROW/8, 256>>>(negp, idxp);
    conv_kernel<64,64,64,8><<<NB*NPT/8, 128, SM_C2>>>(h1p, idxp, fw2, fg2, fb2, h2p);

    xx_kernel<64><<<NROW/256, 256>>>(h2p, xxp);
    dist_kernel<64><<<dim3(8,8,NB), 256>>>(h2p, xxp, negp);
    topk_kernel<<<NROW/8, 256>>>(negp, idxp);
    conv_kernel<64,64,128,4><<<NB*NPT/4, 128, SM_C3>>>(h2p, idxp, fw3, fg3, fb3, s0p);  // s0p reused as S3

    // ---- fuse + attention (all 16 batches) ----
    emb_kernel<<<NROW/32, 128, SM_EW>>>(h3p, s0p, ew, eg, ebv, embp);

    float* att_out = out + 8;                       // att1 (b 0..7) then att2 (b 8..15), contiguous
    colsum_part<<<dim3(NB, 8), 128>>>(embp, partp);
    gc2_kernel<<<NB, 128>>>(partp, att_w, gcp);
    sc_kernel<<<NROW/4, 128>>>(embp, gcp, att_out);
    pool_part<<<dim3(NB, 8), 128>>>(embp, att_out, partp);
    pool_fin<<<NB, 128>>>(partp, ep);

    final_kernel<<<BB, 128>>>(ep, tn_w, tn_wb, tn_b, fc1_w, fc1_b, sc_w, sc_b, out);
}